// round 8
// baseline (speedup 1.0000x reference)
#include <cuda_runtime.h>
#include <stdint.h>
#include <math.h>

// ---------------------------------------------------------------------------
// Static device scratch (no runtime allocation allowed).
// ---------------------------------------------------------------------------
#define BIG_ELEMS 44302336   // 4*64*416*416  (also >= 4*128*208*208)
__device__ float g_buf0[BIG_ELEMS];
__device__ float g_buf1[BIG_ELEMS];
__device__ float g_t[346112];        // 4*128*26*26
__device__ float g_w16[16];
__device__ float g_bnsc[128];
__device__ float g_bnsh[128];

// ---------------------------------------------------------------------------
// f32x2 packed-math helpers (Blackwell sm_100a packed fp32 pipe)
// ---------------------------------------------------------------------------
typedef unsigned long long ull;

__device__ __forceinline__ ull pack2(float lo, float hi) {
    ull r; asm("mov.b64 %0, {%1, %2};" : "=l"(r) : "f"(lo), "f"(hi)); return r;
}
__device__ __forceinline__ void unpack2(ull v, float& lo, float& hi) {
    asm("mov.b64 {%0, %1}, %2;" : "=f"(lo), "=f"(hi) : "l"(v));
}
__device__ __forceinline__ void fma2(ull& a, ull b, ull c) {
    asm("fma.rn.f32x2 %0, %1, %2, %0;" : "+l"(a) : "l"(b), "l"(c));
}

// ---------------------------------------------------------------------------
// cp.async helpers
// ---------------------------------------------------------------------------
__device__ __forceinline__ void cpa4(unsigned int dst, const float* src, bool ok) {
    asm volatile("cp.async.ca.shared.global [%0], [%1], 4, %2;\n"
                 :: "r"(dst), "l"(src), "r"(ok ? 4u : 0u));
}
__device__ __forceinline__ void cpa_commit() {
    asm volatile("cp.async.commit_group;\n");
}
template<int N>
__device__ __forceinline__ void cpa_wait() {
    asm volatile("cp.async.wait_group %0;\n" :: "n"(N));
}

// ---------------------------------------------------------------------------
// Direct 3x3 conv, pad=1, stride=1, NCHW, fp32 (packed f32x2 math).
// 256 threads -> 64x32 output tile, 2 rows x 4 cols per thread (two f32x2
// pairs per row). COPB output channels per block. 2-stage cp.async pipeline.
// Weight path identical to R4: LDS.32 broadcast + pack2 (crossbar-optimal).
// ACT: 0=none 1=relu 2=sigmoid; BN: per-channel scale/shift after relu.
// ---------------------------------------------------------------------------
#define HSTRIDE 68
#define HELEMS  2244   // 34 rows x 66 cols

template<int COPB, int ACT, bool BN>
__global__ void __launch_bounds__(256, 1)
conv3x3_k(const float* __restrict__ in, const float* __restrict__ wt,
          const float* __restrict__ bias, float* __restrict__ out,
          int N, int Cin, int Co, int H, int W,
          const float* __restrict__ bnsc, const float* __restrict__ bnsh)
{
    __shared__ __align__(16) float s_in[2][34 * HSTRIDE];
    __shared__ __align__(16) float s_w[2][COPB * 9];

    const int tid = threadIdx.x;
    const int tx = tid & 15;          // x: 4-wide columns
    const int ty = tid >> 4;          // y: 2-tall rows
    const int tile_x = blockIdx.x * 64;
    const int tile_y = blockIdx.y * 32;
    const int co_blocks = Co / COPB;
    const int n   = blockIdx.z / co_blocks;
    const int co0 = (blockIdx.z % co_blocks) * COPB;

    const float* inN = in + (size_t)n * Cin * H * W;

    // ---- hoist ci-invariant halo-load addressing (34 x 66 halo) ----
    int  h_off[9]; int h_sm[9]; bool h_ok[9];
#pragma unroll
    for (int k = 0; k < 9; k++) {
        int idx = tid + k * 256;
        h_ok[k] = false; h_off[k] = 0; h_sm[k] = 0;
        if (idx < HELEMS) {
            int row = idx / 66, col = idx % 66;
            int gy = tile_y - 1 + row;
            int gx = tile_x - 1 + col;
            bool ok = (gy >= 0 && gy < H && gx >= 0 && gx < W);
            h_ok[k]  = ok;
            h_off[k] = ok ? gy * W + gx : 0;
            h_sm[k]  = row * HSTRIDE + col;
        }
    }
    const bool w_ld = (tid < COPB * 9);
    size_t w_base = 0;
    if (w_ld) {
        int j = tid / 9, k = tid - j * 9;
        w_base = ((size_t)(co0 + j) * Cin) * 9 + k;   // + ci*9 per stage
    }

    unsigned int s_in_a[2], s_w_a[2];
    s_in_a[0] = (unsigned int)__cvta_generic_to_shared(&s_in[0][0]);
    s_in_a[1] = (unsigned int)__cvta_generic_to_shared(&s_in[1][0]);
    s_w_a[0]  = (unsigned int)__cvta_generic_to_shared(&s_w[0][0]);
    s_w_a[1]  = (unsigned int)__cvta_generic_to_shared(&s_w[1][0]);

    auto issue_stage = [&](int ci, int s) {
        const float* inC = inN + (size_t)ci * H * W;
#pragma unroll
        for (int k = 0; k < 9; k++) {
            if (tid + k * 256 < HELEMS)
                cpa4(s_in_a[s] + (unsigned int)h_sm[k] * 4u, inC + h_off[k], h_ok[k]);
        }
        if (w_ld)
            cpa4(s_w_a[s] + (unsigned int)tid * 4u, wt + w_base + (size_t)ci * 9, true);
        cpa_commit();
    };

    // acc[j][0]=row0 x(0,1)  [1]=row0 x(2,3)  [2]=row1 x(0,1)  [3]=row1 x(2,3)
    ull acc[COPB][4];
#pragma unroll
    for (int j = 0; j < COPB; j++)
#pragma unroll
        for (int p = 0; p < 4; p++) acc[j][p] = 0ull;

    issue_stage(0, 0);

    for (int ci = 0; ci < Cin; ci++) {
        const int cur = ci & 1;
        if (ci + 1 < Cin) {
            issue_stage(ci + 1, cur ^ 1);
            cpa_wait<1>();
        } else {
            cpa_wait<0>();
        }
        __syncthreads();

        const float* si = s_in[cur];

        // 4 input rows x 5 overlapping x-pairs (cols 4tx .. 4tx+5)
        ull P[4][5];
#pragma unroll
        for (int r = 0; r < 4; r++) {
            const int base = (2 * ty + r) * HSTRIDE + 4 * tx;
            float2 q0 = *(const float2*)&si[base];
            float2 q1 = *(const float2*)&si[base + 2];
            float2 q2 = *(const float2*)&si[base + 4];
            P[r][0] = pack2(q0.x, q0.y);
            P[r][1] = pack2(q0.y, q1.x);
            P[r][2] = pack2(q1.x, q1.y);
            P[r][3] = pack2(q1.y, q2.x);
            P[r][4] = pack2(q2.x, q2.y);
        }

#pragma unroll
        for (int j = 0; j < COPB; j++) {
            const float* w9 = &s_w[cur][j * 9];
#pragma unroll
            for (int ky = 0; ky < 3; ky++) {
#pragma unroll
                for (int kx = 0; kx < 3; kx++) {
                    float w = w9[ky * 3 + kx];      // LDS.32 broadcast
                    ull wp = pack2(w, w);
                    fma2(acc[j][0], P[ky    ][kx    ], wp);
                    fma2(acc[j][1], P[ky    ][kx + 2], wp);
                    fma2(acc[j][2], P[ky + 1][kx    ], wp);
                    fma2(acc[j][3], P[ky + 1][kx + 2], wp);
                }
            }
        }
        __syncthreads();
    }

    // ---- epilogue ----
    const int ox = tile_x + 4 * tx;     // 4-aligned; W%4==0 -> all-in or all-out
    const int oy = tile_y + 2 * ty;
    if (ox < W) {
#pragma unroll
        for (int j = 0; j < COPB; j++) {
            int co = co0 + j;
            float bv = __ldg(&bias[co]);
            float sc = 1.f, sh = 0.f;
            if (BN) { sc = __ldg(&bnsc[co]); sh = __ldg(&bnsh[co]); }
            float v[8];
            unpack2(acc[j][0], v[0], v[1]);
            unpack2(acc[j][1], v[2], v[3]);
            unpack2(acc[j][2], v[4], v[5]);
            unpack2(acc[j][3], v[6], v[7]);
#pragma unroll
            for (int p = 0; p < 8; p++) {
                float t = v[p] + bv;
                if (ACT == 1) t = fmaxf(t, 0.f);
                if (BN)       t = t * sc + sh;
                if (ACT == 2) t = 1.f / (1.f + expf(-t));
                v[p] = t;
            }
            float* outC = out + (((size_t)n * Co + co) * H) * W;
            if (oy < H)
                *(float4*)&outC[(size_t)oy * W + ox] = make_float4(v[0], v[1], v[2], v[3]);
            if (oy + 1 < H)
                *(float4*)&outC[(size_t)(oy + 1) * W + ox] = make_float4(v[4], v[5], v[6], v[7]);
        }
    }
}

// ---------------------------------------------------------------------------
// 2x2 max pool, stride 2
// ---------------------------------------------------------------------------
__global__ void maxpool_k(const float* __restrict__ in, float* __restrict__ out,
                          int NC, int H, int W)
{
    int Ho = H >> 1, Wo = W >> 1;
    long total = (long)NC * Ho * Wo;
    for (long i = blockIdx.x * (long)blockDim.x + threadIdx.x; i < total;
         i += (long)gridDim.x * blockDim.x) {
        int xo = (int)(i % Wo);
        int yo = (int)((i / Wo) % Ho);
        long nc = i / ((long)Wo * Ho);
        const float* p = in + (size_t)nc * H * W + (size_t)(2 * yo) * W + 2 * xo;
        out[i] = fmaxf(fmaxf(p[0], p[1]), fmaxf(p[W], p[W + 1]));
    }
}

// ---------------------------------------------------------------------------
// Bilinear 2x upsample, align_corners=True
// ---------------------------------------------------------------------------
__global__ void up2_k(const float* __restrict__ in, float* __restrict__ out,
                      int NC, int H, int W)
{
    int Ho = 2 * H, Wo = 2 * W;
    float sy = (float)(H - 1) / (float)(Ho - 1);
    float sx = (float)(W - 1) / (float)(Wo - 1);
    long total = (long)NC * Ho * Wo;
    for (long i = blockIdx.x * (long)blockDim.x + threadIdx.x; i < total;
         i += (long)gridDim.x * blockDim.x) {
        int xo = (int)(i % Wo);
        int yo = (int)((i / Wo) % Ho);
        long nc = i / ((long)Wo * Ho);
        float ys = yo * sy, xs = xo * sx;
        int y0 = (int)floorf(ys), x0 = (int)floorf(xs);
        int y1 = min(y0 + 1, H - 1), x1 = min(x0 + 1, W - 1);
        float wy = ys - (float)y0, wx = xs - (float)x0;
        const float* p = in + (size_t)nc * H * W;
        float a = p[y0 * W + x0] * (1.f - wy) + p[y1 * W + x0] * wy;
        float b = p[y0 * W + x1] * (1.f - wy) + p[y1 * W + x1] * wy;
        out[i] = a * (1.f - wx) + b * wx;
    }
}

// ---------------------------------------------------------------------------
// Block attention, collapsed:
//   t = fold of 16 blocks; w16[m,n] = <block(m,n), t>/676; y = x * w16[blk]
// ---------------------------------------------------------------------------
__global__ void attn_t_k(const float* __restrict__ x, float* __restrict__ t)
{
    const int total = 4 * 128 * 26 * 26;
    for (int i = blockIdx.x * blockDim.x + threadIdx.x; i < total;
         i += gridDim.x * blockDim.x) {
        int w  = i % 26;
        int h  = (i / 26) % 26;
        int bc = i / 676;
        const float* p = x + (size_t)bc * 104 * 104;
        float s = 0.f;
#pragma unroll
        for (int k = 0; k < 4; k++)
#pragma unroll
            for (int l = 0; l < 4; l++)
                s += p[(k * 26 + h) * 104 + l * 26 + w];
        t[i] = s;
    }
}

__global__ void attn_w_k(const float* __restrict__ x, const float* __restrict__ t,
                         float* __restrict__ w16)
{
    const int mn = blockIdx.x;
    const int m = mn >> 2, nn = mn & 3;
    const int total = 4 * 128 * 26 * 26;
    float s = 0.f;
    for (int i = threadIdx.x; i < total; i += blockDim.x) {
        int w  = i % 26;
        int h  = (i / 26) % 26;
        int bc = i / 676;
        s += x[(size_t)bc * 104 * 104 + (m * 26 + h) * 104 + nn * 26 + w] * t[i];
    }
    __shared__ float red[1024];
    red[threadIdx.x] = s;
    __syncthreads();
    for (int st = blockDim.x >> 1; st > 0; st >>= 1) {
        if (threadIdx.x < st) red[threadIdx.x] += red[threadIdx.x + st];
        __syncthreads();
    }
    if (threadIdx.x == 0) w16[mn] = red[0] * (1.f / 676.f);
}

__global__ void attn_scale_k(float* __restrict__ x, const float* __restrict__ w16)
{
    const long total = 4L * 128 * 104 * 104;
    for (long i = blockIdx.x * (long)blockDim.x + threadIdx.x; i < total;
         i += (long)gridDim.x * blockDim.x) {
        int j  = (int)(i % 104);
        int ii = (int)((i / 104) % 104);
        x[i] *= w16[(ii / 26) * 4 + (j / 26)];
    }
}

// ---------------------------------------------------------------------------
// Fold BN (inference) into per-channel scale/shift.
// ---------------------------------------------------------------------------
__global__ void bn_prep_k(const float* __restrict__ g, const float* __restrict__ b,
                          const float* __restrict__ m, const float* __restrict__ v,
                          float* __restrict__ sc, float* __restrict__ sh, int C)
{
    int c = blockIdx.x * blockDim.x + threadIdx.x;
    if (c < C) {
        float s = g[c] / sqrtf(v[c] + 1e-5f);
        sc[c] = s;
        sh[c] = b[c] - m[c] * s;
    }
}

// ---------------------------------------------------------------------------
// Host orchestration (graph-capturable: kernel launches only, default stream)
// ---------------------------------------------------------------------------
static inline dim3 conv_grid(int W, int H, int N, int Co, int copb)
{
    return dim3((W + 63) / 64, (H + 31) / 32, N * (Co / copb));
}

extern "C" void kernel_launch(void* const* d_in, const int* in_sizes, int n_in,
                              void* d_out, int out_size)
{
    (void)in_sizes; (void)n_in; (void)out_size;
    const float* x    = (const float*)d_in[0];
    const float* w1   = (const float*)d_in[1];
    const float* b1   = (const float*)d_in[2];
    const float* w2   = (const float*)d_in[3];
    const float* b2   = (const float*)d_in[4];
    const float* w3   = (const float*)d_in[5];
    const float* b3   = (const float*)d_in[6];
    const float* w4   = (const float*)d_in[7];
    const float* b4   = (const float*)d_in[8];
    const float* dw1  = (const float*)d_in[9];
    const float* db1  = (const float*)d_in[10];
    const float* dw2  = (const float*)d_in[11];
    const float* db2  = (const float*)d_in[12];
    const float* dw3  = (const float*)d_in[13];
    const float* db3  = (const float*)d_in[14];
    const float* dw4  = (const float*)d_in[15];
    const float* db4  = (const float*)d_in[16];
    const float* dw5  = (const float*)d_in[17];
    const float* db5  = (const float*)d_in[18];
    const float* bn2g = (const float*)d_in[19];
    const float* bn2b = (const float*)d_in[20];
    const float* bn2m = (const float*)d_in[21];
    const float* bn2v = (const float*)d_in[22];
    const float* bn4g = (const float*)d_in[23];
    const float* bn4b = (const float*)d_in[24];
    const float* bn4m = (const float*)d_in[25];
    const float* bn4v = (const float*)d_in[26];
    float* out = (float*)d_out;

    float *buf0, *buf1, *tb, *w16, *bnsc, *bnsh;
    cudaGetSymbolAddress((void**)&buf0, g_buf0);
    cudaGetSymbolAddress((void**)&buf1, g_buf1);
    cudaGetSymbolAddress((void**)&tb,   g_t);
    cudaGetSymbolAddress((void**)&w16,  g_w16);
    cudaGetSymbolAddress((void**)&bnsc, g_bnsc);
    cudaGetSymbolAddress((void**)&bnsh, g_bnsh);

    // Encoder
    conv3x3_k<8,1,false><<<conv_grid(416, 416, 4, 64, 8), 256>>>(x,    w1, b1, buf0, 4, 3,   64, 416, 416, nullptr, nullptr);
    conv3x3_k<8,1,false><<<conv_grid(416, 416, 4, 64, 8), 256>>>(buf0, w2, b2, buf1, 4, 64,  64, 416, 416, nullptr, nullptr);
    maxpool_k<<<4096, 256>>>(buf1, buf0, 4 * 64, 416, 416);
    conv3x3_k<8,1,false><<<conv_grid(208, 208, 4, 128, 8), 256>>>(buf0, w3, b3, buf1, 4, 64,  128, 208, 208, nullptr, nullptr);
    conv3x3_k<8,1,false><<<conv_grid(208, 208, 4, 128, 8), 256>>>(buf1, w4, b4, buf0, 4, 128, 128, 208, 208, nullptr, nullptr);
    maxpool_k<<<2048, 256>>>(buf0, buf1, 4 * 128, 208, 208);

    // Block attention x2 (in-place on buf1)
    attn_t_k<<<1352, 256>>>(buf1, tb);
    attn_w_k<<<16, 1024>>>(buf1, tb, w16);
    attn_scale_k<<<2048, 256>>>(buf1, w16);
    attn_t_k<<<1352, 256>>>(buf1, tb);
    attn_w_k<<<16, 1024>>>(buf1, tb, w16);
    attn_scale_k<<<2048, 256>>>(buf1, w16);

    // Decoder
    conv3x3_k<8,1,false><<<conv_grid(104, 104, 4, 128, 8), 256>>>(buf1, dw1, db1, buf0, 4, 128, 128, 104, 104, nullptr, nullptr);
    bn_prep_k<<<1, 128>>>(bn2g, bn2b, bn2m, bn2v, bnsc, bnsh, 128);
    conv3x3_k<8,1,true ><<<conv_grid(104, 104, 4, 128, 8), 256>>>(buf0, dw2, db2, buf1, 4, 128, 128, 104, 104, bnsc, bnsh);
    up2_k<<<2048, 256>>>(buf1, buf0, 4 * 128, 104, 104);
    conv3x3_k<8,1,false><<<conv_grid(208, 208, 4, 64, 8), 256>>>(buf0, dw3, db3, buf1, 4, 128, 64, 208, 208, nullptr, nullptr);
    bn_prep_k<<<1, 64>>>(bn4g, bn4b, bn4m, bn4v, bnsc, bnsh, 64);
    conv3x3_k<8,1,true ><<<conv_grid(208, 208, 4, 64, 8), 256>>>(buf1, dw4, db4, buf0, 4, 64, 64, 208, 208, bnsc, bnsh);
    up2_k<<<4096, 256>>>(buf0, buf1, 4 * 64, 208, 208);
    conv3x3_k<2,2,false><<<conv_grid(416, 416, 4, 2, 2), 256>>>(buf1, dw5, db5, out, 4, 64, 2, 416, 416, nullptr, nullptr);
}

// round 9
// speedup vs baseline: 1.1295x; 1.1295x over previous
#include <cuda_runtime.h>
#include <stdint.h>
#include <math.h>

// ---------------------------------------------------------------------------
// Static device scratch (no runtime allocation allowed).
// ---------------------------------------------------------------------------
#define BIG_ELEMS 44302336   // 4*64*416*416  (also >= 4*128*208*208)
__device__ float g_buf0[BIG_ELEMS];
__device__ float g_buf1[BIG_ELEMS];
__device__ float g_t[346112];        // 4*128*26*26
__device__ float g_w16[16];
__device__ float g_bnsc[128];
__device__ float g_bnsh[128];

// ---------------------------------------------------------------------------
// f32x2 packed-math helpers (Blackwell sm_100a packed fp32 pipe)
// ---------------------------------------------------------------------------
typedef unsigned long long ull;

__device__ __forceinline__ ull pack2(float lo, float hi) {
    ull r; asm("mov.b64 %0, {%1, %2};" : "=l"(r) : "f"(lo), "f"(hi)); return r;
}
__device__ __forceinline__ void unpack2(ull v, float& lo, float& hi) {
    asm("mov.b64 {%0, %1}, %2;" : "=f"(lo), "=f"(hi) : "l"(v));
}
__device__ __forceinline__ void fma2(ull& a, ull b, ull c) {
    asm("fma.rn.f32x2 %0, %1, %2, %0;" : "+l"(a) : "l"(b), "l"(c));
}

// ---------------------------------------------------------------------------
// cp.async helpers
// ---------------------------------------------------------------------------
__device__ __forceinline__ void cpa4(unsigned int dst, const float* src, bool ok) {
    asm volatile("cp.async.ca.shared.global [%0], [%1], 4, %2;\n"
                 :: "r"(dst), "l"(src), "r"(ok ? 4u : 0u));
}
__device__ __forceinline__ void cpa_commit() {
    asm volatile("cp.async.commit_group;\n");
}
template<int N>
__device__ __forceinline__ void cpa_wait() {
    asm volatile("cp.async.wait_group %0;\n" :: "n"(N));
}

// ---------------------------------------------------------------------------
// Direct 3x3 conv, pad=1, stride=1, NCHW, fp32 (R4 structure).
// 256 threads -> 32x32 output tile, 2x2 outputs/thread (x-pair packed f32x2),
// COPB output channels per block, 2-stage cp.async pipeline over Cin.
// Change vs R4: COPB=4 + sentinel halo offsets + launch_bounds(256,3)
// to reach 3 CTAs/SM (24 warps) for latency hiding.
// ACT: 0=none 1=relu 2=sigmoid; BN: per-channel scale/shift after relu.
// ---------------------------------------------------------------------------
template<int COPB, int ACT, bool BN>
__global__ void __launch_bounds__(256, 3)
conv3x3_k(const float* __restrict__ in, const float* __restrict__ wt,
          const float* __restrict__ bias, float* __restrict__ out,
          int N, int Cin, int Co, int H, int W,
          const float* __restrict__ bnsc, const float* __restrict__ bnsh)
{
    __shared__ __align__(16) float s_in[2][1160];   // 34x34 halo tile
    __shared__ __align__(16) float s_w[2][COPB * 9];

    const int tid = threadIdx.x;
    const int tx = tid & 15;
    const int ty = tid >> 4;
    const int tile_x = blockIdx.x * 32;
    const int tile_y = blockIdx.y * 32;
    const int co_blocks = Co / COPB;
    const int n   = blockIdx.z / co_blocks;
    const int co0 = (blockIdx.z % co_blocks) * COPB;

    const float* inN = in + (size_t)n * Cin * H * W;

    // ---- hoist ci-invariant halo addressing; -1 = out of bounds ----
    int h_off[5];
#pragma unroll
    for (int k = 0; k < 5; k++) {
        int idx = tid + k * 256;
        h_off[k] = -1;
        if (idx < 1156) {
            int iy = tile_y - 1 + idx / 34;
            int ix = tile_x - 1 + idx % 34;
            if (iy >= 0 && iy < H && ix >= 0 && ix < W)
                h_off[k] = iy * W + ix;
        }
    }

    unsigned int s_in_a[2], s_w_a[2];
    s_in_a[0] = (unsigned int)__cvta_generic_to_shared(&s_in[0][0]);
    s_in_a[1] = (unsigned int)__cvta_generic_to_shared(&s_in[1][0]);
    s_w_a[0]  = (unsigned int)__cvta_generic_to_shared(&s_w[0][0]);
    s_w_a[1]  = (unsigned int)__cvta_generic_to_shared(&s_w[1][0]);

    const bool w_ld = (tid < COPB * 9);
    size_t w_base = 0;
    if (w_ld) {
        int j = tid / 9, k = tid - j * 9;
        w_base = ((size_t)(co0 + j) * Cin) * 9 + k;   // + ci*9 per stage
    }

    auto issue_stage = [&](int ci, int s) {
        const float* inC = inN + (size_t)ci * H * W;
#pragma unroll
        for (int k = 0; k < 5; k++) {
            if (tid + k * 256 < 1156) {
                bool ok = (h_off[k] >= 0);
                cpa4(s_in_a[s] + (unsigned int)(tid + k * 256) * 4u,
                     inC + (ok ? h_off[k] : 0), ok);
            }
        }
        if (w_ld)
            cpa4(s_w_a[s] + (unsigned int)tid * 4u, wt + w_base + (size_t)ci * 9, true);
        cpa_commit();
    };

    ull accp[COPB][2];
#pragma unroll
    for (int j = 0; j < COPB; j++) { accp[j][0] = 0ull; accp[j][1] = 0ull; }

    issue_stage(0, 0);

    for (int ci = 0; ci < Cin; ci++) {
        const int cur = ci & 1;
        if (ci + 1 < Cin) {
            issue_stage(ci + 1, cur ^ 1);
            cpa_wait<1>();
        } else {
            cpa_wait<0>();
        }
        __syncthreads();

        const float* si = s_in[cur];

        // 4 rows x 3 overlapping x-pairs
        ull P[4][3];
#pragma unroll
        for (int dy = 0; dy < 4; dy++) {
            const int base = (2 * ty + dy) * 34 + 2 * tx;
            float2 a = *(const float2*)&si[base];
            float2 b = *(const float2*)&si[base + 2];
            P[dy][0] = pack2(a.x, a.y);
            P[dy][1] = pack2(a.y, b.x);
            P[dy][2] = pack2(b.x, b.y);
        }

#pragma unroll
        for (int j = 0; j < COPB; j++) {
            const float* w9 = &s_w[cur][j * 9];
#pragma unroll
            for (int ky = 0; ky < 3; ky++) {
#pragma unroll
                for (int kx = 0; kx < 3; kx++) {
                    float w = w9[ky * 3 + kx];      // LDS.32 broadcast
                    ull wp = pack2(w, w);
                    fma2(accp[j][0], P[ky    ][kx], wp);
                    fma2(accp[j][1], P[ky + 1][kx], wp);
                }
            }
        }
        __syncthreads();
    }

    // ---- epilogue ----
    const int ox = tile_x + 2 * tx;
    const int oy = tile_y + 2 * ty;
    if (ox < W) {
#pragma unroll
        for (int j = 0; j < COPB; j++) {
            int co = co0 + j;
            if (co < Co) {
                float bv = __ldg(&bias[co]);
                float sc = 1.f, sh = 0.f;
                if (BN) { sc = __ldg(&bnsc[co]); sh = __ldg(&bnsh[co]); }
                float v0, v1, v2, v3;
                unpack2(accp[j][0], v0, v1);
                unpack2(accp[j][1], v2, v3);
                v0 += bv; v1 += bv; v2 += bv; v3 += bv;
                if (ACT == 1) {
                    v0 = fmaxf(v0, 0.f); v1 = fmaxf(v1, 0.f);
                    v2 = fmaxf(v2, 0.f); v3 = fmaxf(v3, 0.f);
                }
                if (BN) {
                    v0 = v0 * sc + sh; v1 = v1 * sc + sh;
                    v2 = v2 * sc + sh; v3 = v3 * sc + sh;
                }
                if (ACT == 2) {
                    v0 = 1.f / (1.f + expf(-v0)); v1 = 1.f / (1.f + expf(-v1));
                    v2 = 1.f / (1.f + expf(-v2)); v3 = 1.f / (1.f + expf(-v3));
                }
                float* outC = out + (((size_t)n * Co + co) * H) * W;
                if (oy < H)     *(float2*)&outC[(size_t)oy * W + ox]       = make_float2(v0, v1);
                if (oy + 1 < H) *(float2*)&outC[(size_t)(oy + 1) * W + ox] = make_float2(v2, v3);
            }
        }
    }
}

// ---------------------------------------------------------------------------
// 2x2 max pool, stride 2
// ---------------------------------------------------------------------------
__global__ void maxpool_k(const float* __restrict__ in, float* __restrict__ out,
                          int NC, int H, int W)
{
    int Ho = H >> 1, Wo = W >> 1;
    long total = (long)NC * Ho * Wo;
    for (long i = blockIdx.x * (long)blockDim.x + threadIdx.x; i < total;
         i += (long)gridDim.x * blockDim.x) {
        int xo = (int)(i % Wo);
        int yo = (int)((i / Wo) % Ho);
        long nc = i / ((long)Wo * Ho);
        const float* p = in + (size_t)nc * H * W + (size_t)(2 * yo) * W + 2 * xo;
        out[i] = fmaxf(fmaxf(p[0], p[1]), fmaxf(p[W], p[W + 1]));
    }
}

// ---------------------------------------------------------------------------
// Bilinear 2x upsample, align_corners=True
// ---------------------------------------------------------------------------
__global__ void up2_k(const float* __restrict__ in, float* __restrict__ out,
                      int NC, int H, int W)
{
    int Ho = 2 * H, Wo = 2 * W;
    float sy = (float)(H - 1) / (float)(Ho - 1);
    float sx = (float)(W - 1) / (float)(Wo - 1);
    long total = (long)NC * Ho * Wo;
    for (long i = blockIdx.x * (long)blockDim.x + threadIdx.x; i < total;
         i += (long)gridDim.x * blockDim.x) {
        int xo = (int)(i % Wo);
        int yo = (int)((i / Wo) % Ho);
        long nc = i / ((long)Wo * Ho);
        float ys = yo * sy, xs = xo * sx;
        int y0 = (int)floorf(ys), x0 = (int)floorf(xs);
        int y1 = min(y0 + 1, H - 1), x1 = min(x0 + 1, W - 1);
        float wy = ys - (float)y0, wx = xs - (float)x0;
        const float* p = in + (size_t)nc * H * W;
        float a = p[y0 * W + x0] * (1.f - wy) + p[y1 * W + x0] * wy;
        float b = p[y0 * W + x1] * (1.f - wy) + p[y1 * W + x1] * wy;
        out[i] = a * (1.f - wx) + b * wx;
    }
}

// ---------------------------------------------------------------------------
// Block attention, collapsed:
//   t = fold of 16 blocks; w16[m,n] = <block(m,n), t>/676; y = x * w16[blk]
// ---------------------------------------------------------------------------
__global__ void attn_t_k(const float* __restrict__ x, float* __restrict__ t)
{
    const int total = 4 * 128 * 26 * 26;
    for (int i = blockIdx.x * blockDim.x + threadIdx.x; i < total;
         i += gridDim.x * blockDim.x) {
        int w  = i % 26;
        int h  = (i / 26) % 26;
        int bc = i / 676;
        const float* p = x + (size_t)bc * 104 * 104;
        float s = 0.f;
#pragma unroll
        for (int k = 0; k < 4; k++)
#pragma unroll
            for (int l = 0; l < 4; l++)
                s += p[(k * 26 + h) * 104 + l * 26 + w];
        t[i] = s;
    }
}

__global__ void attn_w_k(const float* __restrict__ x, const float* __restrict__ t,
                         float* __restrict__ w16)
{
    const int mn = blockIdx.x;
    const int m = mn >> 2, nn = mn & 3;
    const int total = 4 * 128 * 26 * 26;
    float s = 0.f;
    for (int i = threadIdx.x; i < total; i += blockDim.x) {
        int w  = i % 26;
        int h  = (i / 26) % 26;
        int bc = i / 676;
        s += x[(size_t)bc * 104 * 104 + (m * 26 + h) * 104 + nn * 26 + w] * t[i];
    }
    __shared__ float red[1024];
    red[threadIdx.x] = s;
    __syncthreads();
    for (int st = blockDim.x >> 1; st > 0; st >>= 1) {
        if (threadIdx.x < st) red[threadIdx.x] += red[threadIdx.x + st];
        __syncthreads();
    }
    if (threadIdx.x == 0) w16[mn] = red[0] * (1.f / 676.f);
}

__global__ void attn_scale_k(float* __restrict__ x, const float* __restrict__ w16)
{
    const long total = 4L * 128 * 104 * 104;
    for (long i = blockIdx.x * (long)blockDim.x + threadIdx.x; i < total;
         i += (long)gridDim.x * blockDim.x) {
        int j  = (int)(i % 104);
        int ii = (int)((i / 104) % 104);
        x[i] *= w16[(ii / 26) * 4 + (j / 26)];
    }
}

// ---------------------------------------------------------------------------
// Fold BN (inference) into per-channel scale/shift.
// ---------------------------------------------------------------------------
__global__ void bn_prep_k(const float* __restrict__ g, const float* __restrict__ b,
                          const float* __restrict__ m, const float* __restrict__ v,
                          float* __restrict__ sc, float* __restrict__ sh, int C)
{
    int c = blockIdx.x * blockDim.x + threadIdx.x;
    if (c < C) {
        float s = g[c] / sqrtf(v[c] + 1e-5f);
        sc[c] = s;
        sh[c] = b[c] - m[c] * s;
    }
}

// ---------------------------------------------------------------------------
// Host orchestration (graph-capturable: kernel launches only, default stream)
// ---------------------------------------------------------------------------
static inline dim3 conv_grid(int W, int H, int N, int Co, int copb)
{
    return dim3((W + 31) / 32, (H + 31) / 32, N * ((Co + copb - 1) / copb));
}

extern "C" void kernel_launch(void* const* d_in, const int* in_sizes, int n_in,
                              void* d_out, int out_size)
{
    (void)in_sizes; (void)n_in; (void)out_size;
    const float* x    = (const float*)d_in[0];
    const float* w1   = (const float*)d_in[1];
    const float* b1   = (const float*)d_in[2];
    const float* w2   = (const float*)d_in[3];
    const float* b2   = (const float*)d_in[4];
    const float* w3   = (const float*)d_in[5];
    const float* b3   = (const float*)d_in[6];
    const float* w4   = (const float*)d_in[7];
    const float* b4   = (const float*)d_in[8];
    const float* dw1  = (const float*)d_in[9];
    const float* db1  = (const float*)d_in[10];
    const float* dw2  = (const float*)d_in[11];
    const float* db2  = (const float*)d_in[12];
    const float* dw3  = (const float*)d_in[13];
    const float* db3  = (const float*)d_in[14];
    const float* dw4  = (const float*)d_in[15];
    const float* db4  = (const float*)d_in[16];
    const float* dw5  = (const float*)d_in[17];
    const float* db5  = (const float*)d_in[18];
    const float* bn2g = (const float*)d_in[19];
    const float* bn2b = (const float*)d_in[20];
    const float* bn2m = (const float*)d_in[21];
    const float* bn2v = (const float*)d_in[22];
    const float* bn4g = (const float*)d_in[23];
    const float* bn4b = (const float*)d_in[24];
    const float* bn4m = (const float*)d_in[25];
    const float* bn4v = (const float*)d_in[26];
    float* out = (float*)d_out;

    float *buf0, *buf1, *tb, *w16, *bnsc, *bnsh;
    cudaGetSymbolAddress((void**)&buf0, g_buf0);
    cudaGetSymbolAddress((void**)&buf1, g_buf1);
    cudaGetSymbolAddress((void**)&tb,   g_t);
    cudaGetSymbolAddress((void**)&w16,  g_w16);
    cudaGetSymbolAddress((void**)&bnsc, g_bnsc);
    cudaGetSymbolAddress((void**)&bnsh, g_bnsh);

    // Encoder
    conv3x3_k<4,1,false><<<conv_grid(416, 416, 4, 64, 4), 256>>>(x,    w1, b1, buf0, 4, 3,   64, 416, 416, nullptr, nullptr);
    conv3x3_k<4,1,false><<<conv_grid(416, 416, 4, 64, 4), 256>>>(buf0, w2, b2, buf1, 4, 64,  64, 416, 416, nullptr, nullptr);
    maxpool_k<<<4096, 256>>>(buf1, buf0, 4 * 64, 416, 416);
    conv3x3_k<4,1,false><<<conv_grid(208, 208, 4, 128, 4), 256>>>(buf0, w3, b3, buf1, 4, 64,  128, 208, 208, nullptr, nullptr);
    conv3x3_k<4,1,false><<<conv_grid(208, 208, 4, 128, 4), 256>>>(buf1, w4, b4, buf0, 4, 128, 128, 208, 208, nullptr, nullptr);
    maxpool_k<<<2048, 256>>>(buf0, buf1, 4 * 128, 208, 208);

    // Block attention x2 (in-place on buf1)
    attn_t_k<<<1352, 256>>>(buf1, tb);
    attn_w_k<<<16, 1024>>>(buf1, tb, w16);
    attn_scale_k<<<2048, 256>>>(buf1, w16);
    attn_t_k<<<1352, 256>>>(buf1, tb);
    attn_w_k<<<16, 1024>>>(buf1, tb, w16);
    attn_scale_k<<<2048, 256>>>(buf1, w16);

    // Decoder
    conv3x3_k<4,1,false><<<conv_grid(104, 104, 4, 128, 4), 256>>>(buf1, dw1, db1, buf0, 4, 128, 128, 104, 104, nullptr, nullptr);
    bn_prep_k<<<1, 128>>>(bn2g, bn2b, bn2m, bn2v, bnsc, bnsh, 128);
    conv3x3_k<4,1,true ><<<conv_grid(104, 104, 4, 128, 4), 256>>>(buf0, dw2, db2, buf1, 4, 128, 128, 104, 104, bnsc, bnsh);
    up2_k<<<2048, 256>>>(buf1, buf0, 4 * 128, 104, 104);
    conv3x3_k<4,1,false><<<conv_grid(208, 208, 4, 64, 4), 256>>>(buf0, dw3, db3, buf1, 4, 128, 64, 208, 208, nullptr, nullptr);
    bn_prep_k<<<1, 64>>>(bn4g, bn4b, bn4m, bn4v, bnsc, bnsh, 64);
    conv3x3_k<4,1,true ><<<conv_grid(208, 208, 4, 64, 4), 256>>>(buf1, dw4, db4, buf0, 4, 64, 64, 208, 208, bnsc, bnsh);
    up2_k<<<4096, 256>>>(buf0, buf1, 4 * 64, 208, 208);
    conv3x3_k<2,2,false><<<conv_grid(416, 416, 4, 2, 2), 256>>>(buf1, dw5, db5, out, 4, 64, 2, 416, 416, nullptr, nullptr);
}

// round 13
// speedup vs baseline: 1.1513x; 1.0193x over previous
#include <cuda_runtime.h>
#include <stdint.h>
#include <math.h>

// ---------------------------------------------------------------------------
// Static device scratch (no runtime allocation allowed).
// ---------------------------------------------------------------------------
#define BIG_ELEMS 44302336   // 4*64*416*416
__device__ float g_buf0[BIG_ELEMS];
__device__ float g_buf1[BIG_ELEMS];
__device__ float g_whi[700000];      // tf32-hi weights [kk][co][ci]
__device__ float g_wlo[700000];      // tf32-lo weights [kk][co][ci]
__device__ float g_t[346112];        // 4*128*26*26
__device__ float g_w16[16];
__device__ float g_bnsc[192];        // bn2 @0, bn4 @128
__device__ float g_bnsh[192];

// weight offsets (floats)
#define T_C2 0        // 64*64*9
#define T_C3 36864    // 128*64*9
#define T_C4 110592   // 128*128*9
#define T_D1 258048
#define T_D2 405504
#define T_D3 552960   // 64*128*9
#define T_D4 626688   // 64*64*9

// ---------------------------------------------------------------------------
// helpers
// ---------------------------------------------------------------------------
typedef unsigned long long ull;

__device__ __forceinline__ float tf32r(float x) {
    unsigned u; asm("cvt.rna.tf32.f32 %0, %1;" : "=r"(u) : "f"(x));
    return __uint_as_float(u);
}
__device__ __forceinline__ ull pack2(float lo, float hi) {
    ull r; asm("mov.b64 %0, {%1, %2};" : "=l"(r) : "f"(lo), "f"(hi)); return r;
}
__device__ __forceinline__ void unpack2(ull v, float& lo, float& hi) {
    asm("mov.b64 {%0, %1}, %2;" : "=f"(lo), "=f"(hi) : "l"(v));
}
__device__ __forceinline__ void fma2(ull& a, ull b, ull c) {
    asm("fma.rn.f32x2 %0, %1, %2, %0;" : "+l"(a) : "l"(b), "l"(c));
}
__device__ __forceinline__ void cpa4(unsigned int dst, const float* src, bool ok) {
    asm volatile("cp.async.ca.shared.global [%0], [%1], 4, %2;\n"
                 :: "r"(dst), "l"(src), "r"(ok ? 4u : 0u));
}
__device__ __forceinline__ void cpa_commit() {
    asm volatile("cp.async.commit_group;\n");
}
template<int N>
__device__ __forceinline__ void cpa_wait() {
    asm volatile("cp.async.wait_group %0;\n" :: "n"(N));
}
__device__ __forceinline__ void mma8(float* acc, unsigned a0, unsigned a1,
                                     unsigned a2, unsigned a3,
                                     unsigned b0, unsigned b1) {
    asm volatile(
        "mma.sync.aligned.m16n8k8.row.col.f32.tf32.tf32.f32 "
        "{%0,%1,%2,%3}, {%4,%5,%6,%7}, {%8,%9}, {%0,%1,%2,%3};\n"
        : "+f"(acc[0]), "+f"(acc[1]), "+f"(acc[2]), "+f"(acc[3])
        : "r"(a0), "r"(a1), "r"(a2), "r"(a3), "r"(b0), "r"(b1));
}

// ---------------------------------------------------------------------------
// Weight prep: hi/lo tf32 split, transposed to [kk][co][ci]
// ---------------------------------------------------------------------------
__global__ void wprep_k(const float* __restrict__ w, float* __restrict__ whi,
                        float* __restrict__ wlo, int Cin, int Co)
{
    int total = Co * Cin * 9;
    for (int i = blockIdx.x * blockDim.x + threadIdx.x; i < total;
         i += gridDim.x * blockDim.x) {
        int kk = i % 9;
        int ci = (i / 9) % Cin;
        int co = i / (9 * Cin);
        float v = w[i];
        float h = tf32r(v);
        size_t o = (size_t)kk * Co * Cin + (size_t)co * Cin + ci;
        whi[o] = h;
        wlo[o] = tf32r(v - h);
    }
}

// ---------------------------------------------------------------------------
// Tensor-core 3x3 conv, hi/lo split with SPLIT ACCUMULATORS:
//   acc_main += H*H          (exact products, large scale)
//   acc_small += H*M + M*H + M*M   (small scale, preserved precision)
//   result = acc_main + acc_small
// Block: 256 thr (8 warps) -> 32x16 px tile x 16 co.  K=8 ci per mma,
// 9 taps.  2-stage cp.async; per-stage in-place hi/lo split.
// Dynamic smem: raw0 raw1 lo = 3*4928 floats = 59136 B.
// ---------------------------------------------------------------------------
#define CISTRIDE 616
#define HALO_R   612
#define STAGE_ELEMS (8 * CISTRIDE)   // 4928
#define TCONV_SMEM (3 * STAGE_ELEMS * 4)

template<bool BN>
__global__ void __launch_bounds__(256, 2)
tconv_k(const float* __restrict__ in,
        const float* __restrict__ whi, const float* __restrict__ wlo,
        const float* __restrict__ bias, float* __restrict__ out,
        int N, int Cin, int Co, int H, int W,
        const float* __restrict__ bnsc, const float* __restrict__ bnsh)
{
    extern __shared__ __align__(16) float dsm[];
    float* s_raw[2] = { dsm, dsm + STAGE_ELEMS };   // raw -> becomes hi in place
    float* s_lo     = dsm + 2 * STAGE_ELEMS;

    const int tid  = threadIdx.x;
    const int lane = tid & 31;
    const int warp = tid >> 5;
    const int g  = lane >> 2;
    const int tg = lane & 3;

    const int tile_x = blockIdx.x * 32;
    const int tile_y = blockIdx.y * 16;
    const int cob = Co >> 4;
    const int n   = blockIdx.z / cob;
    const int co0 = (blockIdx.z % cob) << 4;
    const int HW = H * W;

    const float* inN = in + (size_t)n * Cin * HW;

    // ---- hoist halo addressing (ci-chunk-invariant) ----
    int h_src[20]; unsigned hmask = 0;
#pragma unroll
    for (int k = 0; k < 20; k++) {
        int idx = tid + k * 256;
        h_src[k] = 0;
        if (idx < STAGE_ELEMS) {
            int ci  = idx / CISTRIDE;
            int rem = idx - ci * CISTRIDE;
            if (rem < HALO_R) {
                int row = rem / 34;
                int col = rem - row * 34;
                int gy = tile_y - 1 + row;
                int gx = tile_x - 1 + col;
                if (gy >= 0 && gy < H && gx >= 0 && gx < W) {
                    h_src[k] = ci * HW + gy * W + gx;
                    hmask |= 1u << k;
                }
            }
        }
    }

    unsigned s_a[2];
    s_a[0] = (unsigned)__cvta_generic_to_shared(s_raw[0]);
    s_a[1] = (unsigned)__cvta_generic_to_shared(s_raw[1]);

    auto issue_stage = [&](int stg, int s) {
        const float* base = inN + (size_t)(stg * 8) * HW;
#pragma unroll
        for (int k = 0; k < 20; k++) {
            int idx = tid + k * 256;
            if (idx < STAGE_ELEMS)
                cpa4(s_a[s] + (unsigned)idx * 4u, base + h_src[k], (hmask >> k) & 1u);
        }
        cpa_commit();
    };

    float accm[8][4];   // main: H*H
    float accs[8][4];   // small: H*M + M*H + M*M
#pragma unroll
    for (int t = 0; t < 8; t++)
#pragma unroll
        for (int i = 0; i < 4; i++) { accm[t][i] = 0.f; accs[t][i] = 0.f; }

    const int S = Cin >> 3;
    issue_stage(0, 0);

    const float* wAh = whi + (size_t)(co0 + g) * Cin + tg;
    const float* wAl = wlo + (size_t)(co0 + g) * Cin + tg;
    const int CoCin = Co * Cin;
    const int bbase = tg * CISTRIDE + g;

    for (int s = 0; s < S; s++) {
        const int cur = s & 1;
        if (s + 1 < S) { issue_stage(s + 1, cur ^ 1); cpa_wait<1>(); }
        else            cpa_wait<0>();
        __syncthreads();

        // in-place hi/lo split of the stage tile
        float* raw = s_raw[cur];
#pragma unroll
        for (int k = 0; k < 20; k++) {
            int idx = tid + k * 256;
            if (idx < STAGE_ELEMS) {
                float x = raw[idx];
                float h = tf32r(x);
                raw[idx]  = h;
                s_lo[idx] = tf32r(x - h);
            }
        }
        __syncthreads();

        const unsigned* sph = (const unsigned*)raw;
        const unsigned* spl = (const unsigned*)s_lo;
        const int cib = s * 8;

#pragma unroll
        for (int kk = 0; kk < 9; kk++) {
            const int ky = kk / 3;
            const int kx = kk - 3 * ky;
            const size_t wo = (size_t)kk * CoCin + cib;
            const float* aph = wAh + wo;
            const float* apl = wAl + wo;
            unsigned ah0 = __float_as_uint(__ldg(aph));
            unsigned ah1 = __float_as_uint(__ldg(aph + 8 * Cin));
            unsigned ah2 = __float_as_uint(__ldg(aph + 4));
            unsigned ah3 = __float_as_uint(__ldg(aph + 8 * Cin + 4));
            unsigned al0 = __float_as_uint(__ldg(apl));
            unsigned al1 = __float_as_uint(__ldg(apl + 8 * Cin));
            unsigned al2 = __float_as_uint(__ldg(apl + 4));
            unsigned al3 = __float_as_uint(__ldg(apl + 8 * Cin + 4));
            const int koff = ky * 34 + kx + bbase;
#pragma unroll
            for (int t = 0; t < 8; t++) {
                const int addr = koff + (2 * warp + (t >> 2)) * 34 + (t & 3) * 8;
                unsigned bh0 = sph[addr];
                unsigned bh1 = sph[addr + 4 * CISTRIDE];
                unsigned bl0 = spl[addr];
                unsigned bl1 = spl[addr + 4 * CISTRIDE];
                mma8(accm[t], ah0, ah1, ah2, ah3, bh0, bh1);   // H*H -> main
                mma8(accs[t], ah0, ah1, ah2, ah3, bl0, bl1);   // H*M -> small
                mma8(accs[t], al0, al1, al2, al3, bh0, bh1);   // M*H -> small
                mma8(accs[t], al0, al1, al2, al3, bl0, bl1);   // M*M -> small
            }
        }
        __syncthreads();
    }

    // ---- epilogue: merge accumulators, bias + relu (+BN), full fp32 ----
    const int coa = co0 + g;
    const int cb  = co0 + g + 8;
    float ba = __ldg(&bias[coa]), bb = __ldg(&bias[cb]);
    float sca = 1.f, sha = 0.f, scb = 1.f, shb = 0.f;
    if (BN) {
        sca = __ldg(&bnsc[coa]); sha = __ldg(&bnsh[coa]);
        scb = __ldg(&bnsc[cb]);  shb = __ldg(&bnsh[cb]);
    }
    float* outN = out + (size_t)n * Co * HW;
#pragma unroll
    for (int t = 0; t < 8; t++) {
        int y = tile_y + 2 * warp + (t >> 2);
        int x = tile_x + (t & 3) * 8 + 2 * tg;
        if (y < H && x < W) {
            float v0 = fmaxf((accm[t][0] + accs[t][0]) + ba, 0.f);
            float v1 = fmaxf((accm[t][1] + accs[t][1]) + ba, 0.f);
            float v2 = fmaxf((accm[t][2] + accs[t][2]) + bb, 0.f);
            float v3 = fmaxf((accm[t][3] + accs[t][3]) + bb, 0.f);
            if (BN) { v0 = v0 * sca + sha; v1 = v1 * sca + sha;
                      v2 = v2 * scb + shb; v3 = v3 * scb + shb; }
            *(float2*)&outN[(size_t)coa * HW + y * W + x] = make_float2(v0, v1);
            *(float2*)&outN[(size_t)cb  * HW + y * W + x] = make_float2(v2, v3);
        }
    }
}

// ---------------------------------------------------------------------------
// Scalar direct conv (R4 kernel) for conv1 (Cin=3) and dconv5 (Co=2).
// ---------------------------------------------------------------------------
template<int COPB, int ACT>
__global__ void __launch_bounds__(256, 2)
conv3x3_k(const float* __restrict__ in, const float* __restrict__ wt,
          const float* __restrict__ bias, float* __restrict__ out,
          int N, int Cin, int Co, int H, int W)
{
    __shared__ __align__(16) float s_in[2][1160];
    __shared__ __align__(16) float s_w[2][COPB * 9];

    const int tid = threadIdx.x;
    const int tx = tid & 15;
    const int ty = tid >> 4;
    const int tile_x = blockIdx.x * 32;
    const int tile_y = blockIdx.y * 32;
    const int co_blocks = (Co + COPB - 1) / COPB;
    const int n   = blockIdx.z / co_blocks;
    const int co0 = (blockIdx.z % co_blocks) * COPB;

    const float* inN = in + (size_t)n * Cin * H * W;

    int  h_off[5]; bool h_ok[5];
#pragma unroll
    for (int k = 0; k < 5; k++) {
        int idx = tid + k * 256;
        h_ok[k] = false; h_off[k] = 0;
        if (idx < 1156) {
            int iy = tile_y - 1 + idx / 34;
            int ix = tile_x - 1 + idx % 34;
            bool ok = (iy >= 0 && iy < H && ix >= 0 && ix < W);
            h_ok[k] = ok; h_off[k] = ok ? iy * W + ix : 0;
        }
    }
    const bool w_ld = (tid < COPB * 9);
    size_t w_base = 0;
    if (w_ld) {
        int j = tid / 9, k = tid - j * 9;
        w_base = ((size_t)(co0 + j) * Cin) * 9 + k;
    }

    unsigned s_in_a[2], s_w_a[2];
    s_in_a[0] = (unsigned)__cvta_generic_to_shared(&s_in[0][0]);
    s_in_a[1] = (unsigned)__cvta_generic_to_shared(&s_in[1][0]);
    s_w_a[0]  = (unsigned)__cvta_generic_to_shared(&s_w[0][0]);
    s_w_a[1]  = (unsigned)__cvta_generic_to_shared(&s_w[1][0]);

    auto issue_stage = [&](int ci, int s) {
        const float* inC = inN + (size_t)ci * H * W;
#pragma unroll
        for (int k = 0; k < 5; k++) {
            int idx = tid + k * 256;
            if (idx < 1156)
                cpa4(s_in_a[s] + (unsigned)idx * 4u, inC + h_off[k], h_ok[k]);
        }
        if (w_ld)
            cpa4(s_w_a[s] + (unsigned)tid * 4u, wt + w_base + (size_t)ci * 9, true);
        cpa_commit();
    };

    ull accp[COPB][2];
#pragma unroll
    for (int j = 0; j < COPB; j++) { accp[j][0] = 0ull; accp[j][1] = 0ull; }

    issue_stage(0, 0);

    for (int ci = 0; ci < Cin; ci++) {
        const int cur = ci & 1;
        if (ci + 1 < Cin) { issue_stage(ci + 1, cur ^ 1); cpa_wait<1>(); }
        else               cpa_wait<0>();
        __syncthreads();

        const float* si = s_in[cur];
        ull P[4][3];
#pragma unroll
        for (int dy = 0; dy < 4; dy++) {
            const int base = (2 * ty + dy) * 34 + 2 * tx;
            float2 a = *(const float2*)&si[base];
            float2 b = *(const float2*)&si[base + 2];
            P[dy][0] = pack2(a.x, a.y);
            P[dy][1] = pack2(a.y, b.x);
            P[dy][2] = pack2(b.x, b.y);
        }
#pragma unroll
        for (int j = 0; j < COPB; j++) {
            const float* w9 = &s_w[cur][j * 9];
#pragma unroll
            for (int ky = 0; ky < 3; ky++)
#pragma unroll
                for (int kx = 0; kx < 3; kx++) {
                    float w = w9[ky * 3 + kx];
                    ull wp = pack2(w, w);
                    fma2(accp[j][0], P[ky    ][kx], wp);
                    fma2(accp[j][1], P[ky + 1][kx], wp);
                }
        }
        __syncthreads();
    }

    const int ox = tile_x + 2 * tx;
    const int oy = tile_y + 2 * ty;
    if (ox < W) {
#pragma unroll
        for (int j = 0; j < COPB; j++) {
            int co = co0 + j;
            if (co < Co) {
                float bv = __ldg(&bias[co]);
                float v0, v1, v2, v3;
                unpack2(accp[j][0], v0, v1);
                unpack2(accp[j][1], v2, v3);
                v0 += bv; v1 += bv; v2 += bv; v3 += bv;
                if (ACT == 1) {
                    v0 = fmaxf(v0, 0.f); v1 = fmaxf(v1, 0.f);
                    v2 = fmaxf(v2, 0.f); v3 = fmaxf(v3, 0.f);
                }
                if (ACT == 2) {
                    v0 = 1.f / (1.f + expf(-v0)); v1 = 1.f / (1.f + expf(-v1));
                    v2 = 1.f / (1.f + expf(-v2)); v3 = 1.f / (1.f + expf(-v3));
                }
                float* outC = out + (((size_t)n * Co + co) * H) * W;
                if (oy < H)     *(float2*)&outC[(size_t)oy * W + ox]       = make_float2(v0, v1);
                if (oy + 1 < H) *(float2*)&outC[(size_t)(oy + 1) * W + ox] = make_float2(v2, v3);
            }
        }
    }
}

// ---------------------------------------------------------------------------
// 2x2 max pool, stride 2
// ---------------------------------------------------------------------------
__global__ void maxpool_k(const float* __restrict__ in, float* __restrict__ out,
                          int NC, int H, int W)
{
    int Ho = H >> 1, Wo = W >> 1;
    long total = (long)NC * Ho * Wo;
    for (long i = blockIdx.x * (long)blockDim.x + threadIdx.x; i < total;
         i += (long)gridDim.x * blockDim.x) {
        int xo = (int)(i % Wo);
        int yo = (int)((i / Wo) % Ho);
        long nc = i / ((long)Wo * Ho);
        const float* p = in + (size_t)nc * H * W + (size_t)(2 * yo) * W + 2 * xo;
        out[i] = fmaxf(fmaxf(p[0], p[1]), fmaxf(p[W], p[W + 1]));
    }
}

// ---------------------------------------------------------------------------
// Bilinear 2x upsample, align_corners=True
// ---------------------------------------------------------------------------
__global__ void up2_k(const float* __restrict__ in, float* __restrict__ out,
                      int NC, int H, int W)
{
    int Ho = 2 * H, Wo = 2 * W;
    float sy = (float)(H - 1) / (float)(Ho - 1);
    float sx = (float)(W - 1) / (float)(Wo - 1);
    long total = (long)NC * Ho * Wo;
    for (long i = blockIdx.x * (long)blockDim.x + threadIdx.x; i < total;
         i += (long)gridDim.x * blockDim.x) {
        int xo = (int)(i % Wo);
        int yo = (int)((i / Wo) % Ho);
        long nc = i / ((long)Wo * Ho);
        float ys = yo * sy, xs = xo * sx;
        int y0 = (int)floorf(ys), x0 = (int)floorf(xs);
        int y1 = min(y0 + 1, H - 1), x1 = min(x0 + 1, W - 1);
        float wy = ys - (float)y0, wx = xs - (float)x0;
        const float* p = in + (size_t)nc * H * W;
        float a = p[y0 * W + x0] * (1.f - wy) + p[y1 * W + x0] * wy;
        float b = p[y0 * W + x1] * (1.f - wy) + p[y1 * W + x1] * wy;
        out[i] = a * (1.f - wx) + b * wx;
    }
}

// ---------------------------------------------------------------------------
// Block attention, collapsed:
//   t = fold of 16 blocks; w16[m,n] = <block(m,n), t>/676; y = x * w16[blk]
// ---------------------------------------------------------------------------
__global__ void attn_t_k(const float* __restrict__ x, float* __restrict__ t)
{
    const int total = 4 * 128 * 26 * 26;
    for (int i = blockIdx.x * blockDim.x + threadIdx.x; i < total;
         i += gridDim.x * blockDim.x) {
        int w  = i % 26;
        int h  = (i / 26) % 26;
        int bc = i / 676;
        const float* p = x + (size_t)bc * 104 * 104;
        float s = 0.f;
#pragma unroll
        for (int k = 0; k < 4; k++)
#pragma unroll
            for (int l = 0; l < 4; l++)
                s += p[(k * 26 + h) * 104 + l * 26 + w];
        t[i] = s;
    }
}

__global__ void attn_w_k(const float* __restrict__ x, const float* __restrict__ t,
                         float* __restrict__ w16)
{
    const int mn = blockIdx.x;
    const int m = mn >> 2, nn = mn & 3;
    const int total = 4 * 128 * 26 * 26;
    float s = 0.f;
    for (int i = threadIdx.x; i < total; i += blockDim.x) {
        int w  = i % 26;
        int h  = (i / 26) % 26;
        int bc = i / 676;
        s += x[(size_t)bc * 104 * 104 + (m * 26 + h) * 104 + nn * 26 + w] * t[i];
    }
    __shared__ float red[1024];
    red[threadIdx.x] = s;
    __syncthreads();
    for (int st = blockDim.x >> 1; st > 0; st >>= 1) {
        if (threadIdx.x < st) red[threadIdx.x] += red[threadIdx.x + st];
        __syncthreads();
    }
    if (threadIdx.x == 0) w16[mn] = red[0] * (1.f / 676.f);
}

__global__ void attn_scale_k(float* __restrict__ x, const float* __restrict__ w16)
{
    const long total = 4L * 128 * 104 * 104;
    for (long i = blockIdx.x * (long)blockDim.x + threadIdx.x; i < total;
         i += (long)gridDim.x * blockDim.x) {
        int j  = (int)(i % 104);
        int ii = (int)((i / 104) % 104);
        x[i] *= w16[(ii / 26) * 4 + (j / 26)];
    }
}

// ---------------------------------------------------------------------------
// Fold BN into per-channel scale/shift.
// ---------------------------------------------------------------------------
__global__ void bn_prep_k(const float* __restrict__ g, const float* __restrict__ b,
                          const float* __restrict__ m, const float* __restrict__ v,
                          float* __restrict__ sc, float* __restrict__ sh, int C)
{
    int c = blockIdx.x * blockDim.x + threadIdx.x;
    if (c < C) {
        float s = g[c] / sqrtf(v[c] + 1e-5f);
        sc[c] = s;
        sh[c] = b[c] - m[c] * s;
    }
}

// ---------------------------------------------------------------------------
// Host orchestration (graph-capturable: kernel launches only, default stream)
// ---------------------------------------------------------------------------
static inline dim3 sgrid(int W, int H, int N, int Co, int copb)
{
    return dim3((W + 31) / 32, (H + 31) / 32, N * ((Co + copb - 1) / copb));
}
static inline dim3 tgrid(int W, int H, int N, int Co)
{
    return dim3((W + 31) / 32, (H + 15) / 16, N * (Co / 16));
}

extern "C" void kernel_launch(void* const* d_in, const int* in_sizes, int n_in,
                              void* d_out, int out_size)
{
    (void)in_sizes; (void)n_in; (void)out_size;
    const float* x    = (const float*)d_in[0];
    const float* w1   = (const float*)d_in[1];
    const float* b1   = (const float*)d_in[2];
    const float* w2   = (const float*)d_in[3];
    const float* b2   = (const float*)d_in[4];
    const float* w3   = (const float*)d_in[5];
    const float* b3   = (const float*)d_in[6];
    const float* w4   = (const float*)d_in[7];
    const float* b4   = (const float*)d_in[8];
    const float* dw1  = (const float*)d_in[9];
    const float* db1  = (const float*)d_in[10];
    const float* dw2  = (const float*)d_in[11];
    const float* db2  = (const float*)d_in[12];
    const float* dw3  = (const float*)d_in[13];
    const float* db3  = (const float*)d_in[14];
    const float* dw4  = (const float*)d_in[15];
    const float* db4  = (const float*)d_in[16];
    const float* dw5  = (const float*)d_in[17];
    const float* db5  = (const float*)d_in[18];
    const float* bn2g = (const float*)d_in[19];
    const float* bn2b = (const float*)d_in[20];
    const float* bn2m = (const float*)d_in[21];
    const float* bn2v = (const float*)d_in[22];
    const float* bn4g = (const float*)d_in[23];
    const float* bn4b = (const float*)d_in[24];
    const float* bn4m = (const float*)d_in[25];
    const float* bn4v = (const float*)d_in[26];
    float* out = (float*)d_out;

    float *buf0, *buf1, *whi, *wlo, *tb, *w16, *bnsc, *bnsh;
    cudaGetSymbolAddress((void**)&buf0, g_buf0);
    cudaGetSymbolAddress((void**)&buf1, g_buf1);
    cudaGetSymbolAddress((void**)&whi,  g_whi);
    cudaGetSymbolAddress((void**)&wlo,  g_wlo);
    cudaGetSymbolAddress((void**)&tb,   g_t);
    cudaGetSymbolAddress((void**)&w16,  g_w16);
    cudaGetSymbolAddress((void**)&bnsc, g_bnsc);
    cudaGetSymbolAddress((void**)&bnsh, g_bnsh);

    cudaFuncSetAttribute(tconv_k<false>, cudaFuncAttributeMaxDynamicSharedMemorySize, TCONV_SMEM);
    cudaFuncSetAttribute(tconv_k<true >, cudaFuncAttributeMaxDynamicSharedMemorySize, TCONV_SMEM);

    // ---- prep: hi/lo tf32 weights + folded BN ----
    wprep_k<<<144, 256>>>(w2,  whi + T_C2, wlo + T_C2, 64,  64);
    wprep_k<<<288, 256>>>(w3,  whi + T_C3, wlo + T_C3, 64,  128);
    wprep_k<<<576, 256>>>(w4,  whi + T_C4, wlo + T_C4, 128, 128);
    wprep_k<<<576, 256>>>(dw1, whi + T_D1, wlo + T_D1, 128, 128);
    wprep_k<<<576, 256>>>(dw2, whi + T_D2, wlo + T_D2, 128, 128);
    wprep_k<<<288, 256>>>(dw3, whi + T_D3, wlo + T_D3, 128, 64);
    wprep_k<<<144, 256>>>(dw4, whi + T_D4, wlo + T_D4, 64,  64);
    bn_prep_k<<<1, 128>>>(bn2g, bn2b, bn2m, bn2v, bnsc,       bnsh,       128);
    bn_prep_k<<<1, 64 >>>(bn4g, bn4b, bn4m, bn4v, bnsc + 128, bnsh + 128, 64);

    // ---- encoder ----
    conv3x3_k<8,1><<<sgrid(416,416,4,64,8), 256>>>(x, w1, b1, buf0, 4, 3, 64, 416, 416);
    tconv_k<false><<<tgrid(416,416,4,64), 256, TCONV_SMEM>>>(buf0, whi+T_C2, wlo+T_C2, b2, buf1, 4, 64, 64, 416, 416, nullptr, nullptr);
    maxpool_k<<<4096, 256>>>(buf1, buf0, 4*64, 416, 416);
    tconv_k<false><<<tgrid(208,208,4,128), 256, TCONV_SMEM>>>(buf0, whi+T_C3, wlo+T_C3, b3, buf1, 4, 64, 128, 208, 208, nullptr, nullptr);
    tconv_k<false><<<tgrid(208,208,4,128), 256, TCONV_SMEM>>>(buf1, whi+T_C4, wlo+T_C4, b4, buf0, 4, 128, 128, 208, 208, nullptr, nullptr);
    maxpool_k<<<2048, 256>>>(buf0, buf1, 4*128, 208, 208);

    // ---- block attention x2 (in-place on buf1) ----
    attn_t_k<<<1352, 256>>>(buf1, tb);
    attn_w_k<<<16, 1024>>>(buf1, tb, w16);
    attn_scale_k<<<2048, 256>>>(buf1, w16);
    attn_t_k<<<1352, 256>>>(buf1, tb);
    attn_w_k<<<16, 1024>>>(buf1, tb, w16);
    attn_scale_k<<<2048, 256>>>(buf1, w16);

    // ---- decoder ----
    tconv_k<false><<<tgrid(104,104,4,128), 256, TCONV_SMEM>>>(buf1, whi+T_D1, wlo+T_D1, db1, buf0, 4, 128, 128, 104, 104, nullptr, nullptr);
    tconv_k<true ><<<tgrid(104,104,4,128), 256, TCONV_SMEM>>>(buf0, whi+T_D2, wlo+T_D2, db2, buf1, 4, 128, 128, 104, 104, bnsc, bnsh);
    up2_k<<<2048, 256>>>(buf1, buf0, 4*128, 104, 104);
    tconv_k<false><<<tgrid(208,208,4,64), 256, TCONV_SMEM>>>(buf0, whi+T_D3, wlo+T_D3, db3, buf1, 4, 128, 64, 208, 208, nullptr, nullptr);
    tconv_k<true ><<<tgrid(208,208,4,64), 256, TCONV_SMEM>>>(buf1, whi+T_D4, wlo+T_D4, db4, buf0, 4, 64, 64, 208, 208, bnsc + 128, bnsh + 128);
    up2_k<<<4096, 256>>>(buf0, buf1, 4*64, 208, 208);
    conv3x3_k<2,2><<<sgrid(416,416,4,2,2), 256>>>(buf1, dw5, db5, out, 4, 64, 2, 416, 416);
}

// round 14
// speedup vs baseline: 1.2200x; 1.0597x over previous
#include <cuda_runtime.h>
#include <stdint.h>
#include <math.h>

// ---------------------------------------------------------------------------
// Static device scratch (no runtime allocation allowed).
// ---------------------------------------------------------------------------
#define BIG_ELEMS 44302336   // 4*64*416*416
__device__ float g_buf0[BIG_ELEMS];
__device__ float g_buf1[BIG_ELEMS];
__device__ float g_whi[700000];      // tf32-hi weights [kk][co][ci]
__device__ float g_wlo[700000];      // tf32-lo weights [kk][co][ci]
__device__ float g_t[346112];        // 4*128*26*26
__device__ float g_w16[16];
#define ATTN_PB 192
__device__ float g_aw[ATTN_PB * 16]; // attention partial sums
__device__ float g_bnsc[192];        // bn2 @0, bn4 @128
__device__ float g_bnsh[192];

// weight offsets (floats)
#define T_C2 0        // 64*64*9
#define T_C3 36864    // 128*64*9
#define T_C4 110592   // 128*128*9
#define T_D1 258048
#define T_D2 405504
#define T_D3 552960   // 64*128*9
#define T_D4 626688   // 64*64*9

// ---------------------------------------------------------------------------
// helpers
// ---------------------------------------------------------------------------
typedef unsigned long long ull;

__device__ __forceinline__ float tf32r(float x) {
    unsigned u; asm("cvt.rna.tf32.f32 %0, %1;" : "=r"(u) : "f"(x));
    return __uint_as_float(u);
}
__device__ __forceinline__ ull pack2(float lo, float hi) {
    ull r; asm("mov.b64 %0, {%1, %2};" : "=l"(r) : "f"(lo), "f"(hi)); return r;
}
__device__ __forceinline__ void unpack2(ull v, float& lo, float& hi) {
    asm("mov.b64 {%0, %1}, %2;" : "=f"(lo), "=f"(hi) : "l"(v));
}
__device__ __forceinline__ void fma2(ull& a, ull b, ull c) {
    asm("fma.rn.f32x2 %0, %1, %2, %0;" : "+l"(a) : "l"(b), "l"(c));
}
__device__ __forceinline__ void cpa4(unsigned int dst, const float* src, bool ok) {
    asm volatile("cp.async.ca.shared.global [%0], [%1], 4, %2;\n"
                 :: "r"(dst), "l"(src), "r"(ok ? 4u : 0u));
}
__device__ __forceinline__ void cpa_commit() {
    asm volatile("cp.async.commit_group;\n");
}
template<int N>
__device__ __forceinline__ void cpa_wait() {
    asm volatile("cp.async.wait_group %0;\n" :: "n"(N));
}
__device__ __forceinline__ void mma8(float* acc, unsigned a0, unsigned a1,
                                     unsigned a2, unsigned a3,
                                     unsigned b0, unsigned b1) {
    asm volatile(
        "mma.sync.aligned.m16n8k8.row.col.f32.tf32.tf32.f32 "
        "{%0,%1,%2,%3}, {%4,%5,%6,%7}, {%8,%9}, {%0,%1,%2,%3};\n"
        : "+f"(acc[0]), "+f"(acc[1]), "+f"(acc[2]), "+f"(acc[3])
        : "r"(a0), "r"(a1), "r"(a2), "r"(a3), "r"(b0), "r"(b1));
}

// ---------------------------------------------------------------------------
// Weight prep: hi/lo tf32 split, transposed to [kk][co][ci]
// ---------------------------------------------------------------------------
__global__ void wprep_k(const float* __restrict__ w, float* __restrict__ whi,
                        float* __restrict__ wlo, int Cin, int Co)
{
    int total = Co * Cin * 9;
    for (int i = blockIdx.x * blockDim.x + threadIdx.x; i < total;
         i += gridDim.x * blockDim.x) {
        int kk = i % 9;
        int ci = (i / 9) % Cin;
        int co = i / (9 * Cin);
        float v = w[i];
        float h = tf32r(v);
        size_t o = (size_t)kk * Co * Cin + (size_t)co * Cin + ci;
        whi[o] = h;
        wlo[o] = tf32r(v - h);
    }
}

// ---------------------------------------------------------------------------
// Tensor-core 3x3 conv, hi/lo split with SPLIT ACCUMULATORS (3 mma):
//   acc_main += H*H ;  acc_small += H*L + L*H   (L*L ~2^-22 rel: dropped)
// Block: 256 thr (8 warps) -> 32x16 px tile x 16 co.  K=8 ci per mma,
// 9 taps.  2-stage cp.async; per-stage in-place hi/lo split.
// Dynamic smem: raw0 raw1 lo = 3*4928 floats = 59136 B.
// ---------------------------------------------------------------------------
#define CISTRIDE 616
#define HALO_R   612
#define STAGE_ELEMS (8 * CISTRIDE)   // 4928
#define TCONV_SMEM (3 * STAGE_ELEMS * 4)

template<bool BN>
__global__ void __launch_bounds__(256, 2)
tconv_k(const float* __restrict__ in,
        const float* __restrict__ whi, const float* __restrict__ wlo,
        const float* __restrict__ bias, float* __restrict__ out,
        int N, int Cin, int Co, int H, int W,
        const float* __restrict__ bnsc, const float* __restrict__ bnsh)
{
    extern __shared__ __align__(16) float dsm[];
    float* s_raw[2] = { dsm, dsm + STAGE_ELEMS };   // raw -> becomes hi in place
    float* s_lo     = dsm + 2 * STAGE_ELEMS;

    const int tid  = threadIdx.x;
    const int lane = tid & 31;
    const int warp = tid >> 5;
    const int g  = lane >> 2;
    const int tg = lane & 3;

    const int tile_x = blockIdx.x * 32;
    const int tile_y = blockIdx.y * 16;
    const int cob = Co >> 4;
    const int n   = blockIdx.z / cob;
    const int co0 = (blockIdx.z % cob) << 4;
    const int HW = H * W;

    const float* inN = in + (size_t)n * Cin * HW;

    // ---- hoist halo addressing (ci-chunk-invariant) ----
    int h_src[20]; unsigned hmask = 0;
#pragma unroll
    for (int k = 0; k < 20; k++) {
        int idx = tid + k * 256;
        h_src[k] = 0;
        if (idx < STAGE_ELEMS) {
            int ci  = idx / CISTRIDE;
            int rem = idx - ci * CISTRIDE;
            if (rem < HALO_R) {
                int row = rem / 34;
                int col = rem - row * 34;
                int gy = tile_y - 1 + row;
                int gx = tile_x - 1 + col;
                if (gy >= 0 && gy < H && gx >= 0 && gx < W) {
                    h_src[k] = ci * HW + gy * W + gx;
                    hmask |= 1u << k;
                }
            }
        }
    }

    unsigned s_a[2];
    s_a[0] = (unsigned)__cvta_generic_to_shared(s_raw[0]);
    s_a[1] = (unsigned)__cvta_generic_to_shared(s_raw[1]);

    auto issue_stage = [&](int stg, int s) {
        const float* base = inN + (size_t)(stg * 8) * HW;
#pragma unroll
        for (int k = 0; k < 20; k++) {
            int idx = tid + k * 256;
            if (idx < STAGE_ELEMS)
                cpa4(s_a[s] + (unsigned)idx * 4u, base + h_src[k], (hmask >> k) & 1u);
        }
        cpa_commit();
    };

    float accm[8][4];   // main: H*H
    float accs[8][4];   // small: H*L + L*H
#pragma unroll
    for (int t = 0; t < 8; t++)
#pragma unroll
        for (int i = 0; i < 4; i++) { accm[t][i] = 0.f; accs[t][i] = 0.f; }

    const int S = Cin >> 3;
    issue_stage(0, 0);

    const float* wAh = whi + (size_t)(co0 + g) * Cin + tg;
    const float* wAl = wlo + (size_t)(co0 + g) * Cin + tg;
    const int CoCin = Co * Cin;
    const int bbase = tg * CISTRIDE + g;

    for (int s = 0; s < S; s++) {
        const int cur = s & 1;
        if (s + 1 < S) { issue_stage(s + 1, cur ^ 1); cpa_wait<1>(); }
        else            cpa_wait<0>();
        __syncthreads();

        // in-place hi/lo split of the stage tile
        float* raw = s_raw[cur];
#pragma unroll
        for (int k = 0; k < 20; k++) {
            int idx = tid + k * 256;
            if (idx < STAGE_ELEMS) {
                float x = raw[idx];
                float h = tf32r(x);
                raw[idx]  = h;
                s_lo[idx] = tf32r(x - h);
            }
        }
        __syncthreads();

        const unsigned* sph = (const unsigned*)raw;
        const unsigned* spl = (const unsigned*)s_lo;
        const int cib = s * 8;

#pragma unroll
        for (int kk = 0; kk < 9; kk++) {
            const int ky = kk / 3;
            const int kx = kk - 3 * ky;
            const size_t wo = (size_t)kk * CoCin + cib;
            const float* aph = wAh + wo;
            const float* apl = wAl + wo;
            unsigned ah0 = __float_as_uint(__ldg(aph));
            unsigned ah1 = __float_as_uint(__ldg(aph + 8 * Cin));
            unsigned ah2 = __float_as_uint(__ldg(aph + 4));
            unsigned ah3 = __float_as_uint(__ldg(aph + 8 * Cin + 4));
            unsigned al0 = __float_as_uint(__ldg(apl));
            unsigned al1 = __float_as_uint(__ldg(apl + 8 * Cin));
            unsigned al2 = __float_as_uint(__ldg(apl + 4));
            unsigned al3 = __float_as_uint(__ldg(apl + 8 * Cin + 4));
            const int koff = ky * 34 + kx + bbase;
#pragma unroll
            for (int t = 0; t < 8; t++) {
                const int addr = koff + (2 * warp + (t >> 2)) * 34 + (t & 3) * 8;
                unsigned bh0 = sph[addr];
                unsigned bh1 = sph[addr + 4 * CISTRIDE];
                unsigned bl0 = spl[addr];
                unsigned bl1 = spl[addr + 4 * CISTRIDE];
                mma8(accm[t], ah0, ah1, ah2, ah3, bh0, bh1);   // H*H -> main
                mma8(accs[t], ah0, ah1, ah2, ah3, bl0, bl1);   // H*L -> small
                mma8(accs[t], al0, al1, al2, al3, bh0, bh1);   // L*H -> small
            }
        }
        __syncthreads();
    }

    // ---- epilogue: merge accumulators, bias + relu (+BN), full fp32 ----
    const int coa = co0 + g;
    const int cb  = co0 + g + 8;
    float ba = __ldg(&bias[coa]), bb = __ldg(&bias[cb]);
    float sca = 1.f, sha = 0.f, scb = 1.f, shb = 0.f;
    if (BN) {
        sca = __ldg(&bnsc[coa]); sha = __ldg(&bnsh[coa]);
        scb = __ldg(&bnsc[cb]);  shb = __ldg(&bnsh[cb]);
    }
    float* outN = out + (size_t)n * Co * HW;
#pragma unroll
    for (int t = 0; t < 8; t++) {
        int y = tile_y + 2 * warp + (t >> 2);
        int x = tile_x + (t & 3) * 8 + 2 * tg;
        if (y < H && x < W) {
            float v0 = fmaxf((accm[t][0] + accs[t][0]) + ba, 0.f);
            float v1 = fmaxf((accm[t][1] + accs[t][1]) + ba, 0.f);
            float v2 = fmaxf((accm[t][2] + accs[t][2]) + bb, 0.f);
            float v3 = fmaxf((accm[t][3] + accs[t][3]) + bb, 0.f);
            if (BN) { v0 = v0 * sca + sha; v1 = v1 * sca + sha;
                      v2 = v2 * scb + shb; v3 = v3 * scb + shb; }
            *(float2*)&outN[(size_t)coa * HW + y * W + x] = make_float2(v0, v1);
            *(float2*)&outN[(size_t)cb  * HW + y * W + x] = make_float2(v2, v3);
        }
    }
}

// ---------------------------------------------------------------------------
// Scalar direct conv (R4 kernel) for conv1 (Cin=3) and dconv5 (Co=2).
// ---------------------------------------------------------------------------
template<int COPB, int ACT>
__global__ void __launch_bounds__(256, 2)
conv3x3_k(const float* __restrict__ in, const float* __restrict__ wt,
          const float* __restrict__ bias, float* __restrict__ out,
          int N, int Cin, int Co, int H, int W)
{
    __shared__ __align__(16) float s_in[2][1160];
    __shared__ __align__(16) float s_w[2][COPB * 9];

    const int tid = threadIdx.x;
    const int tx = tid & 15;
    const int ty = tid >> 4;
    const int tile_x = blockIdx.x * 32;
    const int tile_y = blockIdx.y * 32;
    const int co_blocks = (Co + COPB - 1) / COPB;
    const int n   = blockIdx.z / co_blocks;
    const int co0 = (blockIdx.z % co_blocks) * COPB;

    const float* inN = in + (size_t)n * Cin * H * W;

    int  h_off[5]; bool h_ok[5];
#pragma unroll
    for (int k = 0; k < 5; k++) {
        int idx = tid + k * 256;
        h_ok[k] = false; h_off[k] = 0;
        if (idx < 1156) {
            int iy = tile_y - 1 + idx / 34;
            int ix = tile_x - 1 + idx % 34;
            bool ok = (iy >= 0 && iy < H && ix >= 0 && ix < W);
            h_ok[k] = ok; h_off[k] = ok ? iy * W + ix : 0;
        }
    }
    const bool w_ld = (tid < COPB * 9);
    size_t w_base = 0;
    if (w_ld) {
        int j = tid / 9, k = tid - j * 9;
        w_base = ((size_t)(co0 + j) * Cin) * 9 + k;
    }

    unsigned s_in_a[2], s_w_a[2];
    s_in_a[0] = (unsigned)__cvta_generic_to_shared(&s_in[0][0]);
    s_in_a[1] = (unsigned)__cvta_generic_to_shared(&s_in[1][0]);
    s_w_a[0]  = (unsigned)__cvta_generic_to_shared(&s_w[0][0]);
    s_w_a[1]  = (unsigned)__cvta_generic_to_shared(&s_w[1][0]);

    auto issue_stage = [&](int ci, int s) {
        const float* inC = inN + (size_t)ci * H * W;
#pragma unroll
        for (int k = 0; k < 5; k++) {
            int idx = tid + k * 256;
            if (idx < 1156)
                cpa4(s_in_a[s] + (unsigned)idx * 4u, inC + h_off[k], h_ok[k]);
        }
        if (w_ld)
            cpa4(s_w_a[s] + (unsigned)tid * 4u, wt + w_base + (size_t)ci * 9, true);
        cpa_commit();
    };

    ull accp[COPB][2];
#pragma unroll
    for (int j = 0; j < COPB; j++) { accp[j][0] = 0ull; accp[j][1] = 0ull; }

    issue_stage(0, 0);

    for (int ci = 0; ci < Cin; ci++) {
        const int cur = ci & 1;
        if (ci + 1 < Cin) { issue_stage(ci + 1, cur ^ 1); cpa_wait<1>(); }
        else               cpa_wait<0>();
        __syncthreads();

        const float* si = s_in[cur];
        ull P[4][3];
#pragma unroll
        for (int dy = 0; dy < 4; dy++) {
            const int base = (2 * ty + dy) * 34 + 2 * tx;
            float2 a = *(const float2*)&si[base];
            float2 b = *(const float2*)&si[base + 2];
            P[dy][0] = pack2(a.x, a.y);
            P[dy][1] = pack2(a.y, b.x);
            P[dy][2] = pack2(b.x, b.y);
        }
#pragma unroll
        for (int j = 0; j < COPB; j++) {
            const float* w9 = &s_w[cur][j * 9];
#pragma unroll
            for (int ky = 0; ky < 3; ky++)
#pragma unroll
                for (int kx = 0; kx < 3; kx++) {
                    float w = w9[ky * 3 + kx];
                    ull wp = pack2(w, w);
                    fma2(accp[j][0], P[ky    ][kx], wp);
                    fma2(accp[j][1], P[ky + 1][kx], wp);
                }
        }
        __syncthreads();
    }

    const int ox = tile_x + 2 * tx;
    const int oy = tile_y + 2 * ty;
    if (ox < W) {
#pragma unroll
        for (int j = 0; j < COPB; j++) {
            int co = co0 + j;
            if (co < Co) {
                float bv = __ldg(&bias[co]);
                float v0, v1, v2, v3;
                unpack2(accp[j][0], v0, v1);
                unpack2(accp[j][1], v2, v3);
                v0 += bv; v1 += bv; v2 += bv; v3 += bv;
                if (ACT == 1) {
                    v0 = fmaxf(v0, 0.f); v1 = fmaxf(v1, 0.f);
                    v2 = fmaxf(v2, 0.f); v3 = fmaxf(v3, 0.f);
                }
                if (ACT == 2) {
                    v0 = 1.f / (1.f + expf(-v0)); v1 = 1.f / (1.f + expf(-v1));
                    v2 = 1.f / (1.f + expf(-v2)); v3 = 1.f / (1.f + expf(-v3));
                }
                float* outC = out + (((size_t)n * Co + co) * H) * W;
                if (oy < H)     *(float2*)&outC[(size_t)oy * W + ox]       = make_float2(v0, v1);
                if (oy + 1 < H) *(float2*)&outC[(size_t)(oy + 1) * W + ox] = make_float2(v2, v3);
            }
        }
    }
}

// ---------------------------------------------------------------------------
// 2x2 max pool, stride 2
// ---------------------------------------------------------------------------
__global__ void maxpool_k(const float* __restrict__ in, float* __restrict__ out,
                          int NC, int H, int W)
{
    int Ho = H >> 1, Wo = W >> 1;
    long total = (long)NC * Ho * Wo;
    for (long i = blockIdx.x * (long)blockDim.x + threadIdx.x; i < total;
         i += (long)gridDim.x * blockDim.x) {
        int xo = (int)(i % Wo);
        int yo = (int)((i / Wo) % Ho);
        long nc = i / ((long)Wo * Ho);
        const float* p = in + (size_t)nc * H * W + (size_t)(2 * yo) * W + 2 * xo;
        out[i] = fmaxf(fmaxf(p[0], p[1]), fmaxf(p[W], p[W + 1]));
    }
}

// ---------------------------------------------------------------------------
// Bilinear 2x upsample, align_corners=True
// ---------------------------------------------------------------------------
__global__ void up2_k(const float* __restrict__ in, float* __restrict__ out,
                      int NC, int H, int W)
{
    int Ho = 2 * H, Wo = 2 * W;
    float sy = (float)(H - 1) / (float)(Ho - 1);
    float sx = (float)(W - 1) / (float)(Wo - 1);
    long total = (long)NC * Ho * Wo;
    for (long i = blockIdx.x * (long)blockDim.x + threadIdx.x; i < total;
         i += (long)gridDim.x * blockDim.x) {
        int xo = (int)(i % Wo);
        int yo = (int)((i / Wo) % Ho);
        long nc = i / ((long)Wo * Ho);
        float ys = yo * sy, xs = xo * sx;
        int y0 = (int)floorf(ys), x0 = (int)floorf(xs);
        int y1 = min(y0 + 1, H - 1), x1 = min(x0 + 1, W - 1);
        float wy = ys - (float)y0, wx = xs - (float)x0;
        const float* p = in + (size_t)nc * H * W;
        float a = p[y0 * W + x0] * (1.f - wy) + p[y1 * W + x0] * wy;
        float b = p[y0 * W + x1] * (1.f - wy) + p[y1 * W + x1] * wy;
        out[i] = a * (1.f - wx) + b * wx;
    }
}

// ---------------------------------------------------------------------------
// Block attention, collapsed:
//   t = fold of 16 blocks; w16[m,n] = <block(m,n), t>/676; y = x * w16[blk]
// Two-phase deterministic reduction for the 16 dot products.
// ---------------------------------------------------------------------------
__global__ void attn_t_k(const float* __restrict__ x, float* __restrict__ t)
{
    const int total = 4 * 128 * 26 * 26;
    for (int i = blockIdx.x * blockDim.x + threadIdx.x; i < total;
         i += gridDim.x * blockDim.x) {
        int w  = i % 26;
        int h  = (i / 26) % 26;
        int bc = i / 676;
        const float* p = x + (size_t)bc * 104 * 104;
        float s = 0.f;
#pragma unroll
        for (int k = 0; k < 4; k++)
#pragma unroll
            for (int l = 0; l < 4; l++)
                s += p[(k * 26 + h) * 104 + l * 26 + w];
        t[i] = s;
    }
}

// Phase A: each of ATTN_PB blocks accumulates partial sums of all 16 weights.
__global__ void attn_w1_k(const float* __restrict__ x, const float* __restrict__ t,
                          float* __restrict__ partial)
{
    const int total = 4 * 128 * 26 * 26;
    float s[16];
#pragma unroll
    for (int j = 0; j < 16; j++) s[j] = 0.f;

    for (int i = blockIdx.x * blockDim.x + threadIdx.x; i < total;
         i += gridDim.x * blockDim.x) {
        int w  = i % 26;
        int h  = (i / 26) % 26;
        int bc = i / 676;
        float tv = t[i];
        const float* px = x + (size_t)bc * 104 * 104 + h * 104 + w;
#pragma unroll
        for (int m = 0; m < 4; m++)
#pragma unroll
            for (int nn = 0; nn < 4; nn++)
                s[m * 4 + nn] += px[(m * 26) * 104 + nn * 26] * tv;
    }

    __shared__ float red[16][257];
#pragma unroll
    for (int j = 0; j < 16; j++) red[j][threadIdx.x] = s[j];
    __syncthreads();
    if (threadIdx.x < 16) {
        float acc = 0.f;
        for (int k = 0; k < 256; k++) acc += red[threadIdx.x][k];
        partial[blockIdx.x * 16 + threadIdx.x] = acc;
    }
}

// Phase B: fold partials into w16.
__global__ void attn_w2_k(const float* __restrict__ partial, float* __restrict__ w16)
{
    int j = threadIdx.x;
    if (j < 16) {
        float acc = 0.f;
        for (int p = 0; p < ATTN_PB; p++) acc += partial[p * 16 + j];
        w16[j] = acc * (1.f / 676.f);
    }
}

__global__ void attn_scale_k(float* __restrict__ x, const float* __restrict__ w16)
{
    const long total = 4L * 128 * 104 * 104;
    for (long i = blockIdx.x * (long)blockDim.x + threadIdx.x; i < total;
         i += (long)gridDim.x * blockDim.x) {
        int j  = (int)(i % 104);
        int ii = (int)((i / 104) % 104);
        x[i] *= w16[(ii / 26) * 4 + (j / 26)];
    }
}

// ---------------------------------------------------------------------------
// Fold BN into per-channel scale/shift.
// ---------------------------------------------------------------------------
__global__ void bn_prep_k(const float* __restrict__ g, const float* __restrict__ b,
                          const float* __restrict__ m, const float* __restrict__ v,
                          float* __restrict__ sc, float* __restrict__ sh, int C)
{
    int c = blockIdx.x * blockDim.x + threadIdx.x;
    if (c < C) {
        float s = g[c] / sqrtf(v[c] + 1e-5f);
        sc[c] = s;
        sh[c] = b[c] - m[c] * s;
    }
}

// ---------------------------------------------------------------------------
// Host orchestration (graph-capturable: kernel launches only, default stream)
// ---------------------------------------------------------------------------
static inline dim3 sgrid(int W, int H, int N, int Co, int copb)
{
    return dim3((W + 31) / 32, (H + 31) / 32, N * ((Co + copb - 1) / copb));
}
static inline dim3 tgrid(int W, int H, int N, int Co)
{
    return dim3((W + 31) / 32, (H + 15) / 16, N * (Co / 16));
}

extern "C" void kernel_launch(void* const* d_in, const int* in_sizes, int n_in,
                              void* d_out, int out_size)
{
    (void)in_sizes; (void)n_in; (void)out_size;
    const float* x    = (const float*)d_in[0];
    const float* w1   = (const float*)d_in[1];
    const float* b1   = (const float*)d_in[2];
    const float* w2   = (const float*)d_in[3];
    const float* b2   = (const float*)d_in[4];
    const float* w3   = (const float*)d_in[5];
    const float* b3   = (const float*)d_in[6];
    const float* w4   = (const float*)d_in[7];
    const float* b4   = (const float*)d_in[8];
    const float* dw1  = (const float*)d_in[9];
    const float* db1  = (const float*)d_in[10];
    const float* dw2  = (const float*)d_in[11];
    const float* db2  = (const float*)d_in[12];
    const float* dw3  = (const float*)d_in[13];
    const float* db3  = (const float*)d_in[14];
    const float* dw4  = (const float*)d_in[15];
    const float* db4  = (const float*)d_in[16];
    const float* dw5  = (const float*)d_in[17];
    const float* db5  = (const float*)d_in[18];
    const float* bn2g = (const float*)d_in[19];
    const float* bn2b = (const float*)d_in[20];
    const float* bn2m = (const float*)d_in[21];
    const float* bn2v = (const float*)d_in[22];
    const float* bn4g = (const float*)d_in[23];
    const float* bn4b = (const float*)d_in[24];
    const float* bn4m = (const float*)d_in[25];
    const float* bn4v = (const float*)d_in[26];
    float* out = (float*)d_out;

    float *buf0, *buf1, *whi, *wlo, *tb, *w16, *aw, *bnsc, *bnsh;
    cudaGetSymbolAddress((void**)&buf0, g_buf0);
    cudaGetSymbolAddress((void**)&buf1, g_buf1);
    cudaGetSymbolAddress((void**)&whi,  g_whi);
    cudaGetSymbolAddress((void**)&wlo,  g_wlo);
    cudaGetSymbolAddress((void**)&tb,   g_t);
    cudaGetSymbolAddress((void**)&w16,  g_w16);
    cudaGetSymbolAddress((void**)&aw,   g_aw);
    cudaGetSymbolAddress((void**)&bnsc, g_bnsc);
    cudaGetSymbolAddress((void**)&bnsh, g_bnsh);

    cudaFuncSetAttribute(tconv_k<false>, cudaFuncAttributeMaxDynamicSharedMemorySize, TCONV_SMEM);
    cudaFuncSetAttribute(tconv_k<true >, cudaFuncAttributeMaxDynamicSharedMemorySize, TCONV_SMEM);

    // ---- prep: hi/lo tf32 weights + folded BN ----
    wprep_k<<<144, 256>>>(w2,  whi + T_C2, wlo + T_C2, 64,  64);
    wprep_k<<<288, 256>>>(w3,  whi + T_C3, wlo + T_C3, 64,  128);
    wprep_k<<<576, 256>>>(w4,  whi + T_C4, wlo + T_C4, 128, 128);
    wprep_k<<<576, 256>>>(dw1, whi + T_D1, wlo + T_D1, 128, 128);
    wprep_k<<<576, 256>>>(dw2, whi + T_D2, wlo + T_D2, 128, 128);
    wprep_k<<<288, 256>>>(dw3, whi + T_D3, wlo + T_D3, 128, 64);
    wprep_k<<<144, 256>>>(dw4, whi + T_D4, wlo + T_D4, 64,  64);
    bn_prep_k<<<1, 128>>>(bn2g, bn2b, bn2m, bn2v, bnsc,       bnsh,       128);
    bn_prep_k<<<1, 64 >>>(bn4g, bn4b, bn4m, bn4v, bnsc + 128, bnsh + 128, 64);

    // ---- encoder ----
    conv3x3_k<8,1><<<sgrid(416,416,4,64,8), 256>>>(x, w1, b1, buf0, 4, 3, 64, 416, 416);
    tconv_k<false><<<tgrid(416,416,4,64), 256, TCONV_SMEM>>>(buf0, whi+T_C2, wlo+T_C2, b2, buf1, 4, 64, 64, 416, 416, nullptr, nullptr);
    maxpool_k<<<4096, 256>>>(buf1, buf0, 4*64, 416, 416);
    tconv_k<false><<<tgrid(208,208,4,128), 256, TCONV_SMEM>>>(buf0, whi+T_C3, wlo+T_C3, b3, buf1, 4, 64, 128, 208, 208, nullptr, nullptr);
    tconv_k<false><<<tgrid(208,208,4,128), 256, TCONV_SMEM>>>(buf1, whi+T_C4, wlo+T_C4, b4, buf0, 4, 128, 128, 208, 208, nullptr, nullptr);
    maxpool_k<<<2048, 256>>>(buf0, buf1, 4*128, 208, 208);

    // ---- block attention x2 (in-place on buf1) ----
    attn_t_k<<<1352, 256>>>(buf1, tb);
    attn_w1_k<<<ATTN_PB, 256>>>(buf1, tb, aw);
    attn_w2_k<<<1, 32>>>(aw, w16);
    attn_scale_k<<<2048, 256>>>(buf1, w16);
    attn_t_k<<<1352, 256>>>(buf1, tb);
    attn_w1_k<<<ATTN_PB, 256>>>(buf1, tb, aw);
    attn_w2_k<<<1, 32>>>(aw, w16);
    attn_scale_k<<<2048, 256>>>(buf1, w16);

    // ---- decoder ----
    tconv_k<false><<<tgrid(104,104,4,128), 256, TCONV_SMEM>>>(buf1, whi+T_D1, wlo+T_D1, db1, buf0, 4, 128, 128, 104, 104, nullptr, nullptr);
    tconv_k<true ><<<tgrid(104,104,4,128), 256, TCONV_SMEM>>>(buf0, whi+T_D2, wlo+T_D2, db2, buf1, 4, 128, 128, 104, 104, bnsc, bnsh);
    up2_k<<<2048, 256>>>(buf1, buf0, 4*128, 104, 104);
    tconv_k<false><<<tgrid(208,208,4,64), 256, TCONV_SMEM>>>(buf0, whi+T_D3, wlo+T_D3, db3, buf1, 4, 128, 64, 208, 208, nullptr, nullptr);
    tconv_k<true ><<<tgrid(208,208,4,64), 256, TCONV_SMEM>>>(buf1, whi+T_D4, wlo+T_D4, db4, buf0, 4, 64, 64, 208, 208, bnsc + 128, bnsh + 128);
    up2_k<<<4096, 256>>>(buf0, buf1, 4*64, 208, 208);
    conv3x3_k<2,2><<<sgrid(416,416,4,2,2), 256>>>(buf1, dw5, db5, out, 4, 64, 2, 416, 416);
}

// round 16
// speedup vs baseline: 1.6083x; 1.3183x over previous
#include <cuda_runtime.h>
#include <stdint.h>
#include <math.h>

// ---------------------------------------------------------------------------
// Static device scratch (no runtime allocation allowed).
// ---------------------------------------------------------------------------
#define BIG_ELEMS 44302336   // 4*64*416*416
__device__ float g_buf0[BIG_ELEMS];
__device__ float g_buf1[BIG_ELEMS];
__device__ float g_whi[700000];      // tf32-hi weights [kk][co][ci]
__device__ float g_wlo[700000];      // tf32-lo weights [kk][co][ci]
__device__ float g_t[346112];        // 4*128*26*26
__device__ float g_w16[16];
#define ATTN_PB 192
__device__ float g_aw[ATTN_PB * 16]; // attention partial sums
__device__ float g_bnsc[192];        // bn2 @0, bn4 @128
__device__ float g_bnsh[192];

// weight offsets (floats)
#define T_C2 0        // 64*64*9
#define T_C3 36864    // 128*64*9
#define T_C4 110592   // 128*128*9
#define T_D1 258048
#define T_D2 405504
#define T_D3 552960   // 64*128*9
#define T_D4 626688   // 64*64*9

// ---------------------------------------------------------------------------
// helpers
// ---------------------------------------------------------------------------
typedef unsigned long long ull;

__device__ __forceinline__ float tf32r(float x) {
    unsigned u; asm("cvt.rna.tf32.f32 %0, %1;" : "=r"(u) : "f"(x));
    return __uint_as_float(u);
}
__device__ __forceinline__ ull pack2(float lo, float hi) {
    ull r; asm("mov.b64 %0, {%1, %2};" : "=l"(r) : "f"(lo), "f"(hi)); return r;
}
__device__ __forceinline__ void unpack2(ull v, float& lo, float& hi) {
    asm("mov.b64 {%0, %1}, %2;" : "=f"(lo), "=f"(hi) : "l"(v));
}
__device__ __forceinline__ void fma2(ull& a, ull b, ull c) {
    asm("fma.rn.f32x2 %0, %1, %2, %0;" : "+l"(a) : "l"(b), "l"(c));
}
__device__ __forceinline__ void cpa4(unsigned int dst, const float* src, bool ok) {
    asm volatile("cp.async.ca.shared.global [%0], [%1], 4, %2;\n"
                 :: "r"(dst), "l"(src), "r"(ok ? 4u : 0u));
}
__device__ __forceinline__ void cpa16(unsigned int dst, const float* src) {
    asm volatile("cp.async.cg.shared.global [%0], [%1], 16;\n"
                 :: "r"(dst), "l"(src));
}
__device__ __forceinline__ void cpa_commit() {
    asm volatile("cp.async.commit_group;\n");
}
template<int N>
__device__ __forceinline__ void cpa_wait() {
    asm volatile("cp.async.wait_group %0;\n" :: "n"(N));
}
__device__ __forceinline__ void mma8(float* acc, unsigned a0, unsigned a1,
                                     unsigned a2, unsigned a3,
                                     unsigned b0, unsigned b1) {
    asm volatile(
        "mma.sync.aligned.m16n8k8.row.col.f32.tf32.tf32.f32 "
        "{%0,%1,%2,%3}, {%4,%5,%6,%7}, {%8,%9}, {%0,%1,%2,%3};\n"
        : "+f"(acc[0]), "+f"(acc[1]), "+f"(acc[2]), "+f"(acc[3])
        : "r"(a0), "r"(a1), "r"(a2), "r"(a3), "r"(b0), "r"(b1));
}

// ---------------------------------------------------------------------------
// Weight prep: hi/lo tf32 split, transposed to [kk][co][ci]
// ---------------------------------------------------------------------------
__global__ void wprep_k(const float* __restrict__ w, float* __restrict__ whi,
                        float* __restrict__ wlo, int Cin, int Co)
{
    int total = Co * Cin * 9;
    for (int i = blockIdx.x * blockDim.x + threadIdx.x; i < total;
         i += gridDim.x * blockDim.x) {
        int kk = i % 9;
        int ci = (i / 9) % Cin;
        int co = i / (9 * Cin);
        float v = w[i];
        float h = tf32r(v);
        size_t o = (size_t)kk * Co * Cin + (size_t)co * Cin + ci;
        whi[o] = h;
        wlo[o] = tf32r(v - h);
    }
}

// ---------------------------------------------------------------------------
// Tensor-core 3x3 conv, hi/lo split with SPLIT ACCUMULATORS (3 mma):
//   acc_main += H*H ;  acc_small += H*L + L*H
// Block: 256 thr (8 warps) -> 32x16 px tile x 16 co.  K=8 ci per mma, 9 taps.
// 2-stage cp.async for BOTH input tile and per-stage weight block; weights
// staged to smem [hl][kk][co][ci pad 12] -> conflict-free LDS A fragments
// (fixes 32-way uncoalesced global A gathers).
// ---------------------------------------------------------------------------
#define CISTRIDE 616
#define HALO_R   612
#define STAGE_ELEMS (8 * CISTRIDE)              // 4928
#define WT_PLANE   (9 * 16 * 12)                // 1728 floats (one of hi/lo)
#define WT_STAGE   (2 * WT_PLANE)               // 3456 floats
#define WT_CHUNKS  (2 * 9 * 16 * 2)             // 576 x 16B chunks
#define SM_FLOATS  (3 * STAGE_ELEMS + 2 * WT_STAGE)   // 14784 + 6912 = 21696
#define TCONV_SMEM (SM_FLOATS * 4)              // 86784 B

template<bool BN>
__global__ void __launch_bounds__(256, 2)
tconv_k(const float* __restrict__ in,
        const float* __restrict__ whi, const float* __restrict__ wlo,
        const float* __restrict__ bias, float* __restrict__ out,
        int N, int Cin, int Co, int H, int W,
        const float* __restrict__ bnsc, const float* __restrict__ bnsh)
{
    extern __shared__ __align__(16) float dsm[];
    float* s_raw[2] = { dsm, dsm + STAGE_ELEMS };   // raw -> becomes hi in place
    float* s_lo     = dsm + 2 * STAGE_ELEMS;
    float* s_wt[2]  = { dsm + 3 * STAGE_ELEMS, dsm + 3 * STAGE_ELEMS + WT_STAGE };

    const int tid  = threadIdx.x;
    const int lane = tid & 31;
    const int warp = tid >> 5;
    const int g  = lane >> 2;
    const int tg = lane & 3;

    const int tile_x = blockIdx.x * 32;
    const int tile_y = blockIdx.y * 16;
    const int cob = Co >> 4;
    const int n   = blockIdx.z / cob;
    const int co0 = (blockIdx.z % cob) << 4;
    const int HW = H * W;

    const float* inN = in + (size_t)n * Cin * HW;

    // ---- hoist halo addressing (ci-chunk-invariant) ----
    int h_src[20]; unsigned hmask = 0;
#pragma unroll
    for (int k = 0; k < 20; k++) {
        int idx = tid + k * 256;
        h_src[k] = 0;
        if (idx < STAGE_ELEMS) {
            int ci  = idx / CISTRIDE;
            int rem = idx - ci * CISTRIDE;
            if (rem < HALO_R) {
                int row = rem / 34;
                int col = rem - row * 34;
                int gy = tile_y - 1 + row;
                int gx = tile_x - 1 + col;
                if (gy >= 0 && gy < H && gx >= 0 && gx < W) {
                    h_src[k] = ci * HW + gy * W + gx;
                    hmask |= 1u << k;
                }
            }
        }
    }

    unsigned s_a[2], s_wa[2];
    s_a[0]  = (unsigned)__cvta_generic_to_shared(s_raw[0]);
    s_a[1]  = (unsigned)__cvta_generic_to_shared(s_raw[1]);
    s_wa[0] = (unsigned)__cvta_generic_to_shared(s_wt[0]);
    s_wa[1] = (unsigned)__cvta_generic_to_shared(s_wt[1]);

    const int CoCin = Co * Cin;

    auto issue_stage = [&](int stg, int s) {
        const float* base = inN + (size_t)(stg * 8) * HW;
#pragma unroll
        for (int k = 0; k < 20; k++) {
            int idx = tid + k * 256;
            if (idx < STAGE_ELEMS)
                cpa4(s_a[s] + (unsigned)idx * 4u, base + h_src[k], (hmask >> k) & 1u);
        }
        // stage weights: [hl][kk][co][ci0..7 pad12], 16B chunks
        const int cib = stg * 8;
#pragma unroll
        for (int k = 0; k < 3; k++) {
            int c = tid + k * 256;
            if (c < WT_CHUNKS) {
                int hl   = c / 288;
                int r    = c - hl * 288;
                int kk   = r >> 5;
                int r2   = r & 31;
                int co   = r2 >> 1;
                int half = r2 & 1;
                const float* src = (hl ? wlo : whi)
                    + (size_t)kk * CoCin + (size_t)(co0 + co) * Cin + cib + half * 4;
                unsigned dst = s_wa[s]
                    + (unsigned)(((hl * 9 + kk) * 16 + co) * 12 + half * 4) * 4u;
                cpa16(dst, src);
            }
        }
        cpa_commit();
    };

    float accm[8][4];   // main: H*H
    float accs[8][4];   // small: H*L + L*H
#pragma unroll
    for (int t = 0; t < 8; t++)
#pragma unroll
        for (int i = 0; i < 4; i++) { accm[t][i] = 0.f; accs[t][i] = 0.f; }

    const int S = Cin >> 3;
    issue_stage(0, 0);

    const int bbase = tg * CISTRIDE + g;

    for (int s = 0; s < S; s++) {
        const int cur = s & 1;
        if (s + 1 < S) { issue_stage(s + 1, cur ^ 1); cpa_wait<1>(); }
        else            cpa_wait<0>();
        __syncthreads();

        // in-place hi/lo split of the input stage tile
        float* raw = s_raw[cur];
#pragma unroll
        for (int k = 0; k < 20; k++) {
            int idx = tid + k * 256;
            if (idx < STAGE_ELEMS) {
                float x = raw[idx];
                float h = tf32r(x);
                raw[idx]  = h;
                s_lo[idx] = tf32r(x - h);
            }
        }
        __syncthreads();

        const unsigned* sph = (const unsigned*)raw;
        const unsigned* spl = (const unsigned*)s_lo;
        const float*    swt = s_wt[cur];

#pragma unroll
        for (int kk = 0; kk < 9; kk++) {
            const int ky = kk / 3;
            const int kx = kk - 3 * ky;
            const int hib = kk * 192;            // (0*9+kk)*16*12
            const int lob = (9 + kk) * 192;
            unsigned ah0 = __float_as_uint(swt[hib + g * 12 + tg]);
            unsigned ah1 = __float_as_uint(swt[hib + (g + 8) * 12 + tg]);
            unsigned ah2 = __float_as_uint(swt[hib + g * 12 + tg + 4]);
            unsigned ah3 = __float_as_uint(swt[hib + (g + 8) * 12 + tg + 4]);
            unsigned al0 = __float_as_uint(swt[lob + g * 12 + tg]);
            unsigned al1 = __float_as_uint(swt[lob + (g + 8) * 12 + tg]);
            unsigned al2 = __float_as_uint(swt[lob + g * 12 + tg + 4]);
            unsigned al3 = __float_as_uint(swt[lob + (g + 8) * 12 + tg + 4]);
            const int koff = ky * 34 + kx + bbase;
#pragma unroll
            for (int t = 0; t < 8; t++) {
                const int addr = koff + (2 * warp + (t >> 2)) * 34 + (t & 3) * 8;
                unsigned bh0 = sph[addr];
                unsigned bh1 = sph[addr + 4 * CISTRIDE];
                unsigned bl0 = spl[addr];
                unsigned bl1 = spl[addr + 4 * CISTRIDE];
                mma8(accm[t], ah0, ah1, ah2, ah3, bh0, bh1);   // H*H -> main
                mma8(accs[t], ah0, ah1, ah2, ah3, bl0, bl1);   // H*L -> small
                mma8(accs[t], al0, al1, al2, al3, bh0, bh1);   // L*H -> small
            }
        }
        __syncthreads();
    }

    // ---- epilogue: merge accumulators, bias + relu (+BN), full fp32 ----
    const int coa = co0 + g;
    const int cb  = co0 + g + 8;
    float ba = __ldg(&bias[coa]), bb = __ldg(&bias[cb]);
    float sca = 1.f, sha = 0.f, scb = 1.f, shb = 0.f;
    if (BN) {
        sca = __ldg(&bnsc[coa]); sha = __ldg(&bnsh[coa]);
        scb = __ldg(&bnsc[cb]);  shb = __ldg(&bnsh[cb]);
    }
    float* outN = out + (size_t)n * Co * HW;
#pragma unroll
    for (int t = 0; t < 8; t++) {
        int y = tile_y + 2 * warp + (t >> 2);
        int x = tile_x + (t & 3) * 8 + 2 * tg;
        if (y < H && x < W) {
            float v0 = fmaxf((accm[t][0] + accs[t][0]) + ba, 0.f);
            float v1 = fmaxf((accm[t][1] + accs[t][1]) + ba, 0.f);
            float v2 = fmaxf((accm[t][2] + accs[t][2]) + bb, 0.f);
            float v3 = fmaxf((accm[t][3] + accs[t][3]) + bb, 0.f);
            if (BN) { v0 = v0 * sca + sha; v1 = v1 * sca + sha;
                      v2 = v2 * scb + shb; v3 = v3 * scb + shb; }
            *(float2*)&outN[(size_t)coa * HW + y * W + x] = make_float2(v0, v1);
            *(float2*)&outN[(size_t)cb  * HW + y * W + x] = make_float2(v2, v3);
        }
    }
}

// ---------------------------------------------------------------------------
// Scalar direct conv (R4 kernel) for conv1 (Cin=3) and dconv5 (Co=2).
// ---------------------------------------------------------------------------
template<int COPB, int ACT>
__global__ void __launch_bounds__(256, 2)
conv3x3_k(const float* __restrict__ in, const float* __restrict__ wt,
          const float* __restrict__ bias, float* __restrict__ out,
          int N, int Cin, int Co, int H, int W)
{
    __shared__ __align__(16) float s_in[2][1160];
    __shared__ __align__(16) float s_w[2][COPB * 9];

    const int tid = threadIdx.x;
    const int tx = tid & 15;
    const int ty = tid >> 4;
    const int tile_x = blockIdx.x * 32;
    const int tile_y = blockIdx.y * 32;
    const int co_blocks = (Co + COPB - 1) / COPB;
    const int n   = blockIdx.z / co_blocks;
    const int co0 = (blockIdx.z % co_blocks) * COPB;

    const float* inN = in + (size_t)n * Cin * H * W;

    int  h_off[5]; bool h_ok[5];
#pragma unroll
    for (int k = 0; k < 5; k++) {
        int idx = tid + k * 256;
        h_ok[k] = false; h_off[k] = 0;
        if (idx < 1156) {
            int iy = tile_y - 1 + idx / 34;
            int ix = tile_x - 1 + idx % 34;
            bool ok = (iy >= 0 && iy < H && ix >= 0 && ix < W);
            h_ok[k] = ok; h_off[k] = ok ? iy * W + ix : 0;
        }
    }
    const bool w_ld = (tid < COPB * 9);
    size_t w_base = 0;
    if (w_ld) {
        int j = tid / 9, k = tid - j * 9;
        w_base = ((size_t)(co0 + j) * Cin) * 9 + k;
    }

    unsigned s_in_a[2], s_w_a[2];
    s_in_a[0] = (unsigned)__cvta_generic_to_shared(&s_in[0][0]);
    s_in_a[1] = (unsigned)__cvta_generic_to_shared(&s_in[1][0]);
    s_w_a[0]  = (unsigned)__cvta_generic_to_shared(&s_w[0][0]);
    s_w_a[1]  = (unsigned)__cvta_generic_to_shared(&s_w[1][0]);

    auto issue_stage = [&](int ci, int s) {
        const float* inC = inN + (size_t)ci * H * W;
#pragma unroll
        for (int k = 0; k < 5; k++) {
            int idx = tid + k * 256;
            if (idx < 1156)
                cpa4(s_in_a[s] + (unsigned)idx * 4u, inC + h_off[k], h_ok[k]);
        }
        if (w_ld)
            cpa4(s_w_a[s] + (unsigned)tid * 4u, wt + w_base + (size_t)ci * 9, true);
        cpa_commit();
    };

    ull accp[COPB][2];
#pragma unroll
    for (int j = 0; j < COPB; j++) { accp[j][0] = 0ull; accp[j][1] = 0ull; }

    issue_stage(0, 0);

    for (int ci = 0; ci < Cin; ci++) {
        const int cur = ci & 1;
        if (ci + 1 < Cin) { issue_stage(ci + 1, cur ^ 1); cpa_wait<1>(); }
        else               cpa_wait<0>();
        __syncthreads();

        const float* si = s_in[cur];
        ull P[4][3];
#pragma unroll
        for (int dy = 0; dy < 4; dy++) {
            const int base = (2 * ty + dy) * 34 + 2 * tx;
            float2 a = *(const float2*)&si[base];
            float2 b = *(const float2*)&si[base + 2];
            P[dy][0] = pack2(a.x, a.y);
            P[dy][1] = pack2(a.y, b.x);
            P[dy][2] = pack2(b.x, b.y);
        }
#pragma unroll
        for (int j = 0; j < COPB; j++) {
            const float* w9 = &s_w[cur][j * 9];
#pragma unroll
            for (int ky = 0; ky < 3; ky++)
#pragma unroll
                for (int kx = 0; kx < 3; kx++) {
                    float w = w9[ky * 3 + kx];
                    ull wp = pack2(w, w);
                    fma2(accp[j][0], P[ky    ][kx], wp);
                    fma2(accp[j][1], P[ky + 1][kx], wp);
                }
        }
        __syncthreads();
    }

    const int ox = tile_x + 2 * tx;
    const int oy = tile_y + 2 * ty;
    if (ox < W) {
#pragma unroll
        for (int j = 0; j < COPB; j++) {
            int co = co0 + j;
            if (co < Co) {
                float bv = __ldg(&bias[co]);
                float v0, v1, v2, v3;
                unpack2(accp[j][0], v0, v1);
                unpack2(accp[j][1], v2, v3);
                v0 += bv; v1 += bv; v2 += bv; v3 += bv;
                if (ACT == 1) {
                    v0 = fmaxf(v0, 0.f); v1 = fmaxf(v1, 0.f);
                    v2 = fmaxf(v2, 0.f); v3 = fmaxf(v3, 0.f);
                }
                if (ACT == 2) {
                    v0 = 1.f / (1.f + expf(-v0)); v1 = 1.f / (1.f + expf(-v1));
                    v2 = 1.f / (1.f + expf(-v2)); v3 = 1.f / (1.f + expf(-v3));
                }
                float* outC = out + (((size_t)n * Co + co) * H) * W;
                if (oy < H)     *(float2*)&outC[(size_t)oy * W + ox]       = make_float2(v0, v1);
                if (oy + 1 < H) *(float2*)&outC[(size_t)(oy + 1) * W + ox] = make_float2(v2, v3);
            }
        }
    }
}

// ---------------------------------------------------------------------------
// 2x2 max pool, stride 2
// ---------------------------------------------------------------------------
__global__ void maxpool_k(const float* __restrict__ in, float* __restrict__ out,
                          int NC, int H, int W)
{
    int Ho = H >> 1, Wo = W >> 1;
    long total = (long)NC * Ho * Wo;
    for (long i = blockIdx.x * (long)blockDim.x + threadIdx.x; i < total;
         i += (long)gridDim.x * blockDim.x) {
        int xo = (int)(i % Wo);
        int yo = (int)((i / Wo) % Ho);
        long nc = i / ((long)Wo * Ho);
        const float* p = in + (size_t)nc * H * W + (size_t)(2 * yo) * W + 2 * xo;
        out[i] = fmaxf(fmaxf(p[0], p[1]), fmaxf(p[W], p[W + 1]));
    }
}

// ---------------------------------------------------------------------------
// Bilinear 2x upsample, align_corners=True
// ---------------------------------------------------------------------------
__global__ void up2_k(const float* __restrict__ in, float* __restrict__ out,
                      int NC, int H, int W)
{
    int Ho = 2 * H, Wo = 2 * W;
    float sy = (float)(H - 1) / (float)(Ho - 1);
    float sx = (float)(W - 1) / (float)(Wo - 1);
    long total = (long)NC * Ho * Wo;
    for (long i = blockIdx.x * (long)blockDim.x + threadIdx.x; i < total;
         i += (long)gridDim.x * blockDim.x) {
        int xo = (int)(i % Wo);
        int yo = (int)((i / Wo) % Ho);
        long nc = i / ((long)Wo * Ho);
        float ys = yo * sy, xs = xo * sx;
        int y0 = (int)floorf(ys), x0 = (int)floorf(xs);
        int y1 = min(y0 + 1, H - 1), x1 = min(x0 + 1, W - 1);
        float wy = ys - (float)y0, wx = xs - (float)x0;
        const float* p = in + (size_t)nc * H * W;
        float a = p[y0 * W + x0] * (1.f - wy) + p[y1 * W + x0] * wy;
        float b = p[y0 * W + x1] * (1.f - wy) + p[y1 * W + x1] * wy;
        out[i] = a * (1.f - wx) + b * wx;
    }
}

// ---------------------------------------------------------------------------
// Block attention, collapsed; two-phase deterministic reduction.
// ---------------------------------------------------------------------------
__global__ void attn_t_k(const float* __restrict__ x, float* __restrict__ t)
{
    const int total = 4 * 128 * 26 * 26;
    for (int i = blockIdx.x * blockDim.x + threadIdx.x; i < total;
         i += gridDim.x * blockDim.x) {
        int w  = i % 26;
        int h  = (i / 26) % 26;
        int bc = i / 676;
        const float* p = x + (size_t)bc * 104 * 104;
        float s = 0.f;
#pragma unroll
        for (int k = 0; k < 4; k++)
#pragma unroll
            for (int l = 0; l < 4; l++)
                s += p[(k * 26 + h) * 104 + l * 26 + w];
        t[i] = s;
    }
}

__global__ void attn_w1_k(const float* __restrict__ x, const float* __restrict__ t,
                          float* __restrict__ partial)
{
    const int total = 4 * 128 * 26 * 26;
    float s[16];
#pragma unroll
    for (int j = 0; j < 16; j++) s[j] = 0.f;

    for (int i = blockIdx.x * blockDim.x + threadIdx.x; i < total;
         i += gridDim.x * blockDim.x) {
        int w  = i % 26;
        int h  = (i / 26) % 26;
        int bc = i / 676;
        float tv = t[i];
        const float* px = x + (size_t)bc * 104 * 104 + h * 104 + w;
#pragma unroll
        for (int m = 0; m < 4; m++)
#pragma unroll
            for (int nn = 0; nn < 4; nn++)
                s[m * 4 + nn] += px[(m * 26) * 104 + nn * 26] * tv;
    }

    __shared__ float red[16][257];
#pragma unroll
    for (int j = 0; j < 16; j++) red[j][threadIdx.x] = s[j];
    __syncthreads();
    if (threadIdx.x < 16) {
        float acc = 0.f;
        for (int k = 0; k < 256; k++) acc += red[threadIdx.x][k];
        partial[blockIdx.x * 16 + threadIdx.x] = acc;
    }
}

__global__ void attn_w2_k(const float* __restrict__ partial, float* __restrict__ w16)
{
    int j = threadIdx.x;
    if (j < 16) {
        float acc = 0.f;
        for (int p = 0; p < ATTN_PB; p++) acc += partial[p * 16 + j];
        w16[j] = acc * (1.f / 676.f);
    }
}

__global__ void attn_scale_k(float* __restrict__ x, const float* __restrict__ w16)
{
    const long total = 4L * 128 * 104 * 104;
    for (long i = blockIdx.x * (long)blockDim.x + threadIdx.x; i < total;
         i += (long)gridDim.x * blockDim.x) {
        int j  = (int)(i % 104);
        int ii = (int)((i / 104) % 104);
        x[i] *= w16[(ii / 26) * 4 + (j / 26)];
    }
}

// ---------------------------------------------------------------------------
// Fold BN into per-channel scale/shift.
// ---------------------------------------------------------------------------
__global__ void bn_prep_k(const float* __restrict__ g, const float* __restrict__ b,
                          const float* __restrict__ m, const float* __restrict__ v,
                          float* __restrict__ sc, float* __restrict__ sh, int C)
{
    int c = blockIdx.x * blockDim.x + threadIdx.x;
    if (c < C) {
        float s = g[c] / sqrtf(v[c] + 1e-5f);
        sc[c] = s;
        sh[c] = b[c] - m[c] * s;
    }
}

// ---------------------------------------------------------------------------
// Host orchestration (graph-capturable: kernel launches only, default stream)
// ---------------------------------------------------------------------------
static inline dim3 sgrid(int W, int H, int N, int Co, int copb)
{
    return dim3((W + 31) / 32, (H + 31) / 32, N * ((Co + copb - 1) / copb));
}
static inline dim3 tgrid(int W, int H, int N, int Co)
{
    return dim3((W + 31) / 32, (H + 15) / 16, N * (Co / 16));
}

extern "C" void kernel_launch(void* const* d_in, const int* in_sizes, int n_in,
                              void* d_out, int out_size)
{
    (void)in_sizes; (void)n_in; (void)out_size;
    const float* x    = (const float*)d_in[0];
    const float* w1   = (const float*)d_in[1];
    const float* b1   = (const float*)d_in[2];
    const float* w2   = (const float*)d_in[3];
    const float* b2   = (const float*)d_in[4];
    const float* w3   = (const float*)d_in[5];
    const float* b3   = (const float*)d_in[6];
    const float* w4   = (const float*)d_in[7];
    const float* b4   = (const float*)d_in[8];
    const float* dw1  = (const float*)d_in[9];
    const float* db1  = (const float*)d_in[10];
    const float* dw2  = (const float*)d_in[11];
    const float* db2  = (const float*)d_in[12];
    const float* dw3  = (const float*)d_in[13];
    const float* db3  = (const float*)d_in[14];
    const float* dw4  = (const float*)d_in[15];
    const float* db4  = (const float*)d_in[16];
    const float* dw5  = (const float*)d_in[17];
    const float* db5  = (const float*)d_in[18];
    const float* bn2g = (const float*)d_in[19];
    const float* bn2b = (const float*)d_in[20];
    const float* bn2m = (const float*)d_in[21];
    const float* bn2v = (const float*)d_in[22];
    const float* bn4g = (const float*)d_in[23];
    const float* bn4b = (const float*)d_in[24];
    const float* bn4m = (const float*)d_in[25];
    const float* bn4v = (const float*)d_in[26];
    float* out = (float*)d_out;

    float *buf0, *buf1, *whi, *wlo, *tb, *w16, *aw, *bnsc, *bnsh;
    cudaGetSymbolAddress((void**)&buf0, g_buf0);
    cudaGetSymbolAddress((void**)&buf1, g_buf1);
    cudaGetSymbolAddress((void**)&whi,  g_whi);
    cudaGetSymbolAddress((void**)&wlo,  g_wlo);
    cudaGetSymbolAddress((void**)&tb,   g_t);
    cudaGetSymbolAddress((void**)&w16,  g_w16);
    cudaGetSymbolAddress((void**)&aw,   g_aw);
    cudaGetSymbolAddress((void**)&bnsc, g_bnsc);
    cudaGetSymbolAddress((void**)&bnsh, g_bnsh);

    cudaFuncSetAttribute(tconv_k<false>, cudaFuncAttributeMaxDynamicSharedMemorySize, TCONV_SMEM);
    cudaFuncSetAttribute(tconv_k<true >, cudaFuncAttributeMaxDynamicSharedMemorySize, TCONV_SMEM);

    // ---- prep (ordered so ncu -s5 -c1 captures tconv_C2 at launch idx 5) ----
    wprep_k<<<144, 256>>>(w2,  whi + T_C2, wlo + T_C2, 64,  64);   // 0
    wprep_k<<<288, 256>>>(w3,  whi + T_C3, wlo + T_C3, 64,  128);  // 1
    wprep_k<<<576, 256>>>(w4,  whi + T_C4, wlo + T_C4, 128, 128);  // 2
    bn_prep_k<<<1, 128>>>(bn2g, bn2b, bn2m, bn2v, bnsc, bnsh, 128);// 3

    // ---- encoder ----
    conv3x3_k<8,1><<<sgrid(416,416,4,64,8), 256>>>(x, w1, b1, buf0, 4, 3, 64, 416, 416);                       // 4
    tconv_k<false><<<tgrid(416,416,4,64), 256, TCONV_SMEM>>>(buf0, whi+T_C2, wlo+T_C2, b2, buf1, 4, 64, 64, 416, 416, nullptr, nullptr);  // 5 <- profiled
    maxpool_k<<<4096, 256>>>(buf1, buf0, 4*64, 416, 416);
    tconv_k<false><<<tgrid(208,208,4,128), 256, TCONV_SMEM>>>(buf0, whi+T_C3, wlo+T_C3, b3, buf1, 4, 64, 128, 208, 208, nullptr, nullptr);
    tconv_k<false><<<tgrid(208,208,4,128), 256, TCONV_SMEM>>>(buf1, whi+T_C4, wlo+T_C4, b4, buf0, 4, 128, 128, 208, 208, nullptr, nullptr);
    maxpool_k<<<2048, 256>>>(buf0, buf1, 4*128, 208, 208);

    // remaining weight prep (needed by decoder only)
    wprep_k<<<576, 256>>>(dw1, whi + T_D1, wlo + T_D1, 128, 128);
    wprep_k<<<576, 256>>>(dw2, whi + T_D2, wlo + T_D2, 128, 128);
    wprep_k<<<288, 256>>>(dw3, whi + T_D3, wlo + T_D3, 128, 64);
    wprep_k<<<144, 256>>>(dw4, whi + T_D4, wlo + T_D4, 64,  64);
    bn_prep_k<<<1, 64 >>>(bn4g, bn4b, bn4m, bn4v, bnsc + 128, bnsh + 128, 64);

    // ---- block attention x2 (in-place on buf1) ----
    attn_t_k<<<1352, 256>>>(buf1, tb);
    attn_w1_k<<<ATTN_PB, 256>>>(buf1, tb, aw);
    attn_w2_k<<<1, 32>>>(aw, w16);
    attn_scale_k<<<2048, 256>>>(buf1, w16);
    attn_t_k<<<1352, 256>>>(buf1, tb);
    attn_w1_k<<<ATTN_PB, 256>>>(buf1, tb, aw);
    attn_w2_k<<<1, 32>>>(aw, w16);
    attn_scale_k<<<2048, 256>>>(buf1, w16);

    // ---- decoder ----
    tconv_k<false><<<tgrid(104,104,4,128), 256, TCONV_SMEM>>>(buf1, whi+T_D1, wlo+T_D1, db1, buf0, 4, 128, 128, 104, 104, nullptr, nullptr);
    tconv_k<true ><<<tgrid(104,104,4,128), 256, TCONV_SMEM>>>(buf0, whi+T_D2, wlo+T_D2, db2, buf1, 4, 128, 128, 104, 104, bnsc, bnsh);
    up2_k<<<2048, 256>>>(buf1, buf0, 4*128, 104, 104);
    tconv_k<false><<<tgrid(208,208,4,64), 256, TCONV_SMEM>>>(buf0, whi+T_D3, wlo+T_D3, db3, buf1, 4, 128, 64, 208, 208, nullptr, nullptr);
    tconv_k<true ><<<tgrid(208,208,4,64), 256, TCONV_SMEM>>>(buf1, whi+T_D4, wlo+T_D4, db4, buf0, 4, 64, 64, 208, 208, bnsc + 128, bnsh + 128);
    up2_k<<<4096, 256>>>(buf0, buf1, 4*64, 208, 208);
    conv3x3_k<2,2><<<sgrid(416,416,4,2,2), 256>>>(buf1, dw5, db5, out, 4, 64, 2, 416, 416);
}

// round 17
// speedup vs baseline: 1.9832x; 1.2331x over previous
#include <cuda_runtime.h>
#include <stdint.h>
#include <math.h>

// ---------------------------------------------------------------------------
// Static device scratch (no runtime allocation allowed).
// ---------------------------------------------------------------------------
#define BIG_ELEMS 44302336   // 4*64*416*416
__device__ float g_buf0[BIG_ELEMS];
__device__ float g_buf1[BIG_ELEMS];
__device__ float g_whi[700000];      // tf32-hi weights [kk][co][ci]
__device__ float g_wlo[700000];      // tf32-lo weights [kk][co][ci]
__device__ float g_t[346112];        // 4*128*26*26
__device__ float g_w16[16];
#define ATTN_PB 192
__device__ float g_aw[ATTN_PB * 16]; // attention partial sums
__device__ float g_bnsc[192];        // bn2 @0, bn4 @128
__device__ float g_bnsh[192];

// weight offsets (floats)
#define T_C2 0        // 64*64*9
#define T_C3 36864    // 128*64*9
#define T_C4 110592   // 128*128*9
#define T_D1 258048
#define T_D2 405504
#define T_D3 552960   // 64*128*9
#define T_D4 626688   // 64*64*9

// ---------------------------------------------------------------------------
// helpers
// ---------------------------------------------------------------------------
typedef unsigned long long ull;

__device__ __forceinline__ float tf32r(float x) {
    unsigned u; asm("cvt.rna.tf32.f32 %0, %1;" : "=r"(u) : "f"(x));
    return __uint_as_float(u);
}
__device__ __forceinline__ ull pack2(float lo, float hi) {
    ull r; asm("mov.b64 %0, {%1, %2};" : "=l"(r) : "f"(lo), "f"(hi)); return r;
}
__device__ __forceinline__ void unpack2(ull v, float& lo, float& hi) {
    asm("mov.b64 {%0, %1}, %2;" : "=f"(lo), "=f"(hi) : "l"(v));
}
__device__ __forceinline__ void fma2(ull& a, ull b, ull c) {
    asm("fma.rn.f32x2 %0, %1, %2, %0;" : "+l"(a) : "l"(b), "l"(c));
}
__device__ __forceinline__ void cpa4(unsigned int dst, const float* src, bool ok) {
    asm volatile("cp.async.ca.shared.global [%0], [%1], 4, %2;\n"
                 :: "r"(dst), "l"(src), "r"(ok ? 4u : 0u));
}
__device__ __forceinline__ void cpa16(unsigned int dst, const float* src) {
    asm volatile("cp.async.cg.shared.global [%0], [%1], 16;\n"
                 :: "r"(dst), "l"(src));
}
__device__ __forceinline__ void cpa_commit() {
    asm volatile("cp.async.commit_group;\n");
}
template<int N>
__device__ __forceinline__ void cpa_wait() {
    asm volatile("cp.async.wait_group %0;\n" :: "n"(N));
}
__device__ __forceinline__ void mma8(float* acc, unsigned a0, unsigned a1,
                                     unsigned a2, unsigned a3,
                                     unsigned b0, unsigned b1) {
    asm volatile(
        "mma.sync.aligned.m16n8k8.row.col.f32.tf32.tf32.f32 "
        "{%0,%1,%2,%3}, {%4,%5,%6,%7}, {%8,%9}, {%0,%1,%2,%3};\n"
        : "+f"(acc[0]), "+f"(acc[1]), "+f"(acc[2]), "+f"(acc[3])
        : "r"(a0), "r"(a1), "r"(a2), "r"(a3), "r"(b0), "r"(b1));
}

// ---------------------------------------------------------------------------
// Weight prep: hi/lo tf32 split, transposed to [kk][co][ci]
// ---------------------------------------------------------------------------
__global__ void wprep_k(const float* __restrict__ w, float* __restrict__ whi,
                        float* __restrict__ wlo, int Cin, int Co)
{
    int total = Co * Cin * 9;
    for (int i = blockIdx.x * blockDim.x + threadIdx.x; i < total;
         i += gridDim.x * blockDim.x) {
        int kk = i % 9;
        int ci = (i / 9) % Cin;
        int co = i / (9 * Cin);
        float v = w[i];
        float h = tf32r(v);
        size_t o = (size_t)kk * Co * Cin + (size_t)co * Cin + ci;
        whi[o] = h;
        wlo[o] = tf32r(v - h);
    }
}

// ---------------------------------------------------------------------------
// Tensor-core 3x3 conv, hi/lo split with SPLIT ACCUMULATORS (3 mma):
//   acc_main += Bh*Wh ; acc_small += Bl*Wh + Bh*Wl
// B split done IN REGISTERS: bh = raw & ~0x1FFF (== what mma truncation sees),
// bl = raw - bh (exact). No activation split pass, no lo tile, one less barrier.
// Block: 256 thr (8 warps) -> 32x16 px tile x 16 co.  K=8 ci per mma, 9 taps.
// 2-stage cp.async for input tile and staged smem weights.
// Dynamic smem: raw0 raw1 + wt0 wt1 = 2*4928 + 2*3456 floats = 67072 B.
// ---------------------------------------------------------------------------
#define CISTRIDE 616
#define HALO_R   612
#define STAGE_ELEMS (8 * CISTRIDE)              // 4928
#define WT_PLANE   (9 * 16 * 12)                // 1728 floats (one of hi/lo)
#define WT_STAGE   (2 * WT_PLANE)               // 3456 floats
#define WT_CHUNKS  (2 * 9 * 16 * 2)             // 576 x 16B chunks
#define SM_FLOATS  (2 * STAGE_ELEMS + 2 * WT_STAGE)   // 9856 + 6912 = 16768
#define TCONV_SMEM (SM_FLOATS * 4)              // 67072 B

template<bool BN>
__global__ void __launch_bounds__(256, 2)
tconv_k(const float* __restrict__ in,
        const float* __restrict__ whi, const float* __restrict__ wlo,
        const float* __restrict__ bias, float* __restrict__ out,
        int N, int Cin, int Co, int H, int W,
        const float* __restrict__ bnsc, const float* __restrict__ bnsh)
{
    extern __shared__ __align__(16) float dsm[];
    float* s_raw[2] = { dsm, dsm + STAGE_ELEMS };
    float* s_wt[2]  = { dsm + 2 * STAGE_ELEMS, dsm + 2 * STAGE_ELEMS + WT_STAGE };

    const int tid  = threadIdx.x;
    const int lane = tid & 31;
    const int warp = tid >> 5;
    const int g  = lane >> 2;
    const int tg = lane & 3;

    const int tile_x = blockIdx.x * 32;
    const int tile_y = blockIdx.y * 16;
    const int cob = Co >> 4;
    const int n   = blockIdx.z / cob;
    const int co0 = (blockIdx.z % cob) << 4;
    const int HW = H * W;

    const float* inN = in + (size_t)n * Cin * HW;

    // ---- hoist halo addressing (ci-chunk-invariant) ----
    int h_src[20]; unsigned hmask = 0;
#pragma unroll
    for (int k = 0; k < 20; k++) {
        int idx = tid + k * 256;
        h_src[k] = 0;
        if (idx < STAGE_ELEMS) {
            int ci  = idx / CISTRIDE;
            int rem = idx - ci * CISTRIDE;
            if (rem < HALO_R) {
                int row = rem / 34;
                int col = rem - row * 34;
                int gy = tile_y - 1 + row;
                int gx = tile_x - 1 + col;
                if (gy >= 0 && gy < H && gx >= 0 && gx < W) {
                    h_src[k] = ci * HW + gy * W + gx;
                    hmask |= 1u << k;
                }
            }
        }
    }

    unsigned s_a[2], s_wa[2];
    s_a[0]  = (unsigned)__cvta_generic_to_shared(s_raw[0]);
    s_a[1]  = (unsigned)__cvta_generic_to_shared(s_raw[1]);
    s_wa[0] = (unsigned)__cvta_generic_to_shared(s_wt[0]);
    s_wa[1] = (unsigned)__cvta_generic_to_shared(s_wt[1]);

    const int CoCin = Co * Cin;

    auto issue_stage = [&](int stg, int s) {
        const float* base = inN + (size_t)(stg * 8) * HW;
#pragma unroll
        for (int k = 0; k < 20; k++) {
            int idx = tid + k * 256;
            if (idx < STAGE_ELEMS)
                cpa4(s_a[s] + (unsigned)idx * 4u, base + h_src[k], (hmask >> k) & 1u);
        }
        // stage weights: [hl][kk][co][ci0..7 pad12], 16B chunks
        const int cib = stg * 8;
#pragma unroll
        for (int k = 0; k < 3; k++) {
            int c = tid + k * 256;
            if (c < WT_CHUNKS) {
                int hl   = c / 288;
                int r    = c - hl * 288;
                int kk   = r >> 5;
                int r2   = r & 31;
                int co   = r2 >> 1;
                int half = r2 & 1;
                const float* src = (hl ? wlo : whi)
                    + (size_t)kk * CoCin + (size_t)(co0 + co) * Cin + cib + half * 4;
                unsigned dst = s_wa[s]
                    + (unsigned)(((hl * 9 + kk) * 16 + co) * 12 + half * 4) * 4u;
                cpa16(dst, src);
            }
        }
        cpa_commit();
    };

    float accm[8][4];   // main: Bh*Wh
    float accs[8][4];   // small: Bl*Wh + Bh*Wl
#pragma unroll
    for (int t = 0; t < 8; t++)
#pragma unroll
        for (int i = 0; i < 4; i++) { accm[t][i] = 0.f; accs[t][i] = 0.f; }

    const int S = Cin >> 3;
    issue_stage(0, 0);

    const int bbase = tg * CISTRIDE + g;

    for (int s = 0; s < S; s++) {
        const int cur = s & 1;
        if (s + 1 < S) { issue_stage(s + 1, cur ^ 1); cpa_wait<1>(); }
        else            cpa_wait<0>();
        __syncthreads();

        const unsigned* spr = (const unsigned*)s_raw[cur];
        const float*    swt = s_wt[cur];

#pragma unroll
        for (int kk = 0; kk < 9; kk++) {
            const int ky = kk / 3;
            const int kx = kk - 3 * ky;
            const int hib = kk * 192;            // (0*9+kk)*16*12
            const int lob = (9 + kk) * 192;
            unsigned ah0 = __float_as_uint(swt[hib + g * 12 + tg]);
            unsigned ah1 = __float_as_uint(swt[hib + (g + 8) * 12 + tg]);
            unsigned ah2 = __float_as_uint(swt[hib + g * 12 + tg + 4]);
            unsigned ah3 = __float_as_uint(swt[hib + (g + 8) * 12 + tg + 4]);
            unsigned al0 = __float_as_uint(swt[lob + g * 12 + tg]);
            unsigned al1 = __float_as_uint(swt[lob + (g + 8) * 12 + tg]);
            unsigned al2 = __float_as_uint(swt[lob + g * 12 + tg + 4]);
            unsigned al3 = __float_as_uint(swt[lob + (g + 8) * 12 + tg + 4]);
            const int koff = ky * 34 + kx + bbase;
#pragma unroll
            for (int t = 0; t < 8; t++) {
                const int addr = koff + (2 * warp + (t >> 2)) * 34 + (t & 3) * 8;
                unsigned r0 = spr[addr];
                unsigned r1 = spr[addr + 4 * CISTRIDE];
                unsigned bh0 = r0 & 0xFFFFE000u;       // == mma's view of raw
                unsigned bh1 = r1 & 0xFFFFE000u;
                unsigned bl0 = __float_as_uint(
                    __uint_as_float(r0) - __uint_as_float(bh0));   // exact
                unsigned bl1 = __float_as_uint(
                    __uint_as_float(r1) - __uint_as_float(bh1));
                mma8(accm[t], ah0, ah1, ah2, ah3, bh0, bh1);   // Bh*Wh -> main
                mma8(accs[t], ah0, ah1, ah2, ah3, bl0, bl1);   // Bl*Wh -> small
                mma8(accs[t], al0, al1, al2, al3, bh0, bh1);   // Bh*Wl -> small
            }
        }
        __syncthreads();
    }

    // ---- epilogue: merge accumulators, bias + relu (+BN), full fp32 ----
    const int coa = co0 + g;
    const int cb  = co0 + g + 8;
    float ba = __ldg(&bias[coa]), bb = __ldg(&bias[cb]);
    float sca = 1.f, sha = 0.f, scb = 1.f, shb = 0.f;
    if (BN) {
        sca = __ldg(&bnsc[coa]); sha = __ldg(&bnsh[coa]);
        scb = __ldg(&bnsc[cb]);  shb = __ldg(&bnsh[cb]);
    }
    float* outN = out + (size_t)n * Co * HW;
#pragma unroll
    for (int t = 0; t < 8; t++) {
        int y = tile_y + 2 * warp + (t >> 2);
        int x = tile_x + (t & 3) * 8 + 2 * tg;
        if (y < H && x < W) {
            float v0 = fmaxf((accm[t][0] + accs[t][0]) + ba, 0.f);
            float v1 = fmaxf((accm[t][1] + accs[t][1]) + ba, 0.f);
            float v2 = fmaxf((accm[t][2] + accs[t][2]) + bb, 0.f);
            float v3 = fmaxf((accm[t][3] + accs[t][3]) + bb, 0.f);
            if (BN) { v0 = v0 * sca + sha; v1 = v1 * sca + sha;
                      v2 = v2 * scb + shb; v3 = v3 * scb + shb; }
            *(float2*)&outN[(size_t)coa * HW + y * W + x] = make_float2(v0, v1);
            *(float2*)&outN[(size_t)cb  * HW + y * W + x] = make_float2(v2, v3);
        }
    }
}

// ---------------------------------------------------------------------------
// Scalar direct conv (R4 kernel) for conv1 (Cin=3) and dconv5 (Co=2).
// ---------------------------------------------------------------------------
template<int COPB, int ACT>
__global__ void __launch_bounds__(256, 2)
conv3x3_k(const float* __restrict__ in, const float* __restrict__ wt,
          const float* __restrict__ bias, float* __restrict__ out,
          int N, int Cin, int Co, int H, int W)
{
    __shared__ __align__(16) float s_in[2][1160];
    __shared__ __align__(16) float s_w[2][COPB * 9];

    const int tid = threadIdx.x;
    const int tx = tid & 15;
    const int ty = tid >> 4;
    const int tile_x = blockIdx.x * 32;
    const int tile_y = blockIdx.y * 32;
    const int co_blocks = (Co + COPB - 1) / COPB;
    const int n   = blockIdx.z / co_blocks;
    const int co0 = (blockIdx.z % co_blocks) * COPB;

    const float* inN = in + (size_t)n * Cin * H * W;

    int  h_off[5]; bool h_ok[5];
#pragma unroll
    for (int k = 0; k < 5; k++) {
        int idx = tid + k * 256;
        h_ok[k] = false; h_off[k] = 0;
        if (idx < 1156) {
            int iy = tile_y - 1 + idx / 34;
            int ix = tile_x - 1 + idx % 34;
            bool ok = (iy >= 0 && iy < H && ix >= 0 && ix < W);
            h_ok[k] = ok; h_off[k] = ok ? iy * W + ix : 0;
        }
    }
    const bool w_ld = (tid < COPB * 9);
    size_t w_base = 0;
    if (w_ld) {
        int j = tid / 9, k = tid - j * 9;
        w_base = ((size_t)(co0 + j) * Cin) * 9 + k;
    }

    unsigned s_in_a[2], s_w_a[2];
    s_in_a[0] = (unsigned)__cvta_generic_to_shared(&s_in[0][0]);
    s_in_a[1] = (unsigned)__cvta_generic_to_shared(&s_in[1][0]);
    s_w_a[0]  = (unsigned)__cvta_generic_to_shared(&s_w[0][0]);
    s_w_a[1]  = (unsigned)__cvta_generic_to_shared(&s_w[1][0]);

    auto issue_stage = [&](int ci, int s) {
        const float* inC = inN + (size_t)ci * H * W;
#pragma unroll
        for (int k = 0; k < 5; k++) {
            int idx = tid + k * 256;
            if (idx < 1156)
                cpa4(s_in_a[s] + (unsigned)idx * 4u, inC + h_off[k], h_ok[k]);
        }
        if (w_ld)
            cpa4(s_w_a[s] + (unsigned)tid * 4u, wt + w_base + (size_t)ci * 9, true);
        cpa_commit();
    };

    ull accp[COPB][2];
#pragma unroll
    for (int j = 0; j < COPB; j++) { accp[j][0] = 0ull; accp[j][1] = 0ull; }

    issue_stage(0, 0);

    for (int ci = 0; ci < Cin; ci++) {
        const int cur = ci & 1;
        if (ci + 1 < Cin) { issue_stage(ci + 1, cur ^ 1); cpa_wait<1>(); }
        else               cpa_wait<0>();
        __syncthreads();

        const float* si = s_in[cur];
        ull P[4][3];
#pragma unroll
        for (int dy = 0; dy < 4; dy++) {
            const int base = (2 * ty + dy) * 34 + 2 * tx;
            float2 a = *(const float2*)&si[base];
            float2 b = *(const float2*)&si[base + 2];
            P[dy][0] = pack2(a.x, a.y);
            P[dy][1] = pack2(a.y, b.x);
            P[dy][2] = pack2(b.x, b.y);
        }
#pragma unroll
        for (int j = 0; j < COPB; j++) {
            const float* w9 = &s_w[cur][j * 9];
#pragma unroll
            for (int ky = 0; ky < 3; ky++)
#pragma unroll
                for (int kx = 0; kx < 3; kx++) {
                    float w = w9[ky * 3 + kx];
                    ull wp = pack2(w, w);
                    fma2(accp[j][0], P[ky    ][kx], wp);
                    fma2(accp[j][1], P[ky + 1][kx], wp);
                }
        }
        __syncthreads();
    }

    const int ox = tile_x + 2 * tx;
    const int oy = tile_y + 2 * ty;
    if (ox < W) {
#pragma unroll
        for (int j = 0; j < COPB; j++) {
            int co = co0 + j;
            if (co < Co) {
                float bv = __ldg(&bias[co]);
                float v0, v1, v2, v3;
                unpack2(accp[j][0], v0, v1);
                unpack2(accp[j][1], v2, v3);
                v0 += bv; v1 += bv; v2 += bv; v3 += bv;
                if (ACT == 1) {
                    v0 = fmaxf(v0, 0.f); v1 = fmaxf(v1, 0.f);
                    v2 = fmaxf(v2, 0.f); v3 = fmaxf(v3, 0.f);
                }
                if (ACT == 2) {
                    v0 = 1.f / (1.f + expf(-v0)); v1 = 1.f / (1.f + expf(-v1));
                    v2 = 1.f / (1.f + expf(-v2)); v3 = 1.f / (1.f + expf(-v3));
                }
                float* outC = out + (((size_t)n * Co + co) * H) * W;
                if (oy < H)     *(float2*)&outC[(size_t)oy * W + ox]       = make_float2(v0, v1);
                if (oy + 1 < H) *(float2*)&outC[(size_t)(oy + 1) * W + ox] = make_float2(v2, v3);
            }
        }
    }
}

// ---------------------------------------------------------------------------
// 2x2 max pool, stride 2
// ---------------------------------------------------------------------------
__global__ void maxpool_k(const float* __restrict__ in, float* __restrict__ out,
                          int NC, int H, int W)
{
    int Ho = H >> 1, Wo = W >> 1;
    long total = (long)NC * Ho * Wo;
    for (long i = blockIdx.x * (long)blockDim.x + threadIdx.x; i < total;
         i += (long)gridDim.x * blockDim.x) {
        int xo = (int)(i % Wo);
        int yo = (int)((i / Wo) % Ho);
        long nc = i / ((long)Wo * Ho);
        const float* p = in + (size_t)nc * H * W + (size_t)(2 * yo) * W + 2 * xo;
        out[i] = fmaxf(fmaxf(p[0], p[1]), fmaxf(p[W], p[W + 1]));
    }
}

// ---------------------------------------------------------------------------
// Bilinear 2x upsample, align_corners=True
// ---------------------------------------------------------------------------
__global__ void up2_k(const float* __restrict__ in, float* __restrict__ out,
                      int NC, int H, int W)
{
    int Ho = 2 * H, Wo = 2 * W;
    float sy = (float)(H - 1) / (float)(Ho - 1);
    float sx = (float)(W - 1) / (float)(Wo - 1);
    long total = (long)NC * Ho * Wo;
    for (long i = blockIdx.x * (long)blockDim.x + threadIdx.x; i < total;
         i += (long)gridDim.x * blockDim.x) {
        int xo = (int)(i % Wo);
        int yo = (int)((i / Wo) % Ho);
        long nc = i / ((long)Wo * Ho);
        float ys = yo * sy, xs = xo * sx;
        int y0 = (int)floorf(ys), x0 = (int)floorf(xs);
        int y1 = min(y0 + 1, H - 1), x1 = min(x0 + 1, W - 1);
        float wy = ys - (float)y0, wx = xs - (float)x0;
        const float* p = in + (size_t)nc * H * W;
        float a = p[y0 * W + x0] * (1.f - wy) + p[y1 * W + x0] * wy;
        float b = p[y0 * W + x1] * (1.f - wy) + p[y1 * W + x1] * wy;
        out[i] = a * (1.f - wx) + b * wx;
    }
}

// ---------------------------------------------------------------------------
// Block attention, collapsed; two-phase deterministic reduction.
// ---------------------------------------------------------------------------
__global__ void attn_t_k(const float* __restrict__ x, float* __restrict__ t)
{
    const int total = 4 * 128 * 26 * 26;
    for (int i = blockIdx.x * blockDim.x + threadIdx.x; i < total;
         i += gridDim.x * blockDim.x) {
        int w  = i % 26;
        int h  = (i / 26) % 26;
        int bc = i / 676;
        const float* p = x + (size_t)bc * 104 * 104;
        float s = 0.f;
#pragma unroll
        for (int k = 0; k < 4; k++)
#pragma unroll
            for (int l = 0; l < 4; l++)
                s += p[(k * 26 + h) * 104 + l * 26 + w];
        t[i] = s;
    }
}

__global__ void attn_w1_k(const float* __restrict__ x, const float* __restrict__ t,
                          float* __restrict__ partial)
{
    const int total = 4 * 128 * 26 * 26;
    float s[16];
#pragma unroll
    for (int j = 0; j < 16; j++) s[j] = 0.f;

    for (int i = blockIdx.x * blockDim.x + threadIdx.x; i < total;
         i += gridDim.x * blockDim.x) {
        int w  = i % 26;
        int h  = (i / 26) % 26;
        int bc = i / 676;
        float tv = t[i];
        const float* px = x + (size_t)bc * 104 * 104 + h * 104 + w;
#pragma unroll
        for (int m = 0; m < 4; m++)
#pragma unroll
            for (int nn = 0; nn < 4; nn++)
                s[m * 4 + nn] += px[(m * 26) * 104 + nn * 26] * tv;
    }

    __shared__ float red[16][257];
#pragma unroll
    for (int j = 0; j < 16; j++) red[j][threadIdx.x] = s[j];
    __syncthreads();
    if (threadIdx.x < 16) {
        float acc = 0.f;
        for (int k = 0; k < 256; k++) acc += red[threadIdx.x][k];
        partial[blockIdx.x * 16 + threadIdx.x] = acc;
    }
}

__global__ void attn_w2_k(const float* __restrict__ partial, float* __restrict__ w16)
{
    int j = threadIdx.x;
    if (j < 16) {
        float acc = 0.f;
        for (int p = 0; p < ATTN_PB; p++) acc += partial[p * 16 + j];
        w16[j] = acc * (1.f / 676.f);
    }
}

__global__ void attn_scale_k(float* __restrict__ x, const float* __restrict__ w16)
{
    const long total = 4L * 128 * 104 * 104;
    for (long i = blockIdx.x * (long)blockDim.x + threadIdx.x; i < total;
         i += (long)gridDim.x * blockDim.x) {
        int j  = (int)(i % 104);
        int ii = (int)((i / 104) % 104);
        x[i] *= w16[(ii / 26) * 4 + (j / 26)];
    }
}

// ---------------------------------------------------------------------------
// Fold BN into per-channel scale/shift.
// ---------------------------------------------------------------------------
__global__ void bn_prep_k(const float* __restrict__ g, const float* __restrict__ b,
                          const float* __restrict__ m, const float* __restrict__ v,
                          float* __restrict__ sc, float* __restrict__ sh, int C)
{
    int c = blockIdx.x * blockDim.x + threadIdx.x;
    if (c < C) {
        float s = g[c] / sqrtf(v[c] + 1e-5f);
        sc[c] = s;
        sh[c] = b[c] - m[c] * s;
    }
}

// ---------------------------------------------------------------------------
// Host orchestration (graph-capturable: kernel launches only, default stream)
// ---------------------------------------------------------------------------
static inline dim3 sgrid(int W, int H, int N, int Co, int copb)
{
    return dim3((W + 31) / 32, (H + 31) / 32, N * ((Co + copb - 1) / copb));
}
static inline dim3 tgrid(int W, int H, int N, int Co)
{
    return dim3((W + 31) / 32, (H + 15) / 16, N * (Co / 16));
}

extern "C" void kernel_launch(void* const* d_in, const int* in_sizes, int n_in,
                              void* d_out, int out_size)
{
    (void)in_sizes; (void)n_in; (void)out_size;
    const float* x    = (const float*)d_in[0];
    const float* w1   = (const float*)d_in[1];
    const float* b1   = (const float*)d_in[2];
    const float* w2   = (const float*)d_in[3];
    const float* b2   = (const float*)d_in[4];
    const float* w3   = (const float*)d_in[5];
    const float* b3   = (const float*)d_in[6];
    const float* w4   = (const float*)d_in[7];
    const float* b4   = (const float*)d_in[8];
    const float* dw1  = (const float*)d_in[9];
    const float* db1  = (const float*)d_in[10];
    const float* dw2  = (const float*)d_in[11];
    const float* db2  = (const float*)d_in[12];
    const float* dw3  = (const float*)d_in[13];
    const float* db3  = (const float*)d_in[14];
    const float* dw4  = (const float*)d_in[15];
    const float* db4  = (const float*)d_in[16];
    const float* dw5  = (const float*)d_in[17];
    const float* db5  = (const float*)d_in[18];
    const float* bn2g = (const float*)d_in[19];
    const float* bn2b = (const float*)d_in[20];
    const float* bn2m = (const float*)d_in[21];
    const float* bn2v = (const float*)d_in[22];
    const float* bn4g = (const float*)d_in[23];
    const float* bn4b = (const float*)d_in[24];
    const float* bn4m = (const float*)d_in[25];
    const float* bn4v = (const float*)d_in[26];
    float* out = (float*)d_out;

    float *buf0, *buf1, *whi, *wlo, *tb, *w16, *aw, *bnsc, *bnsh;
    cudaGetSymbolAddress((void**)&buf0, g_buf0);
    cudaGetSymbolAddress((void**)&buf1, g_buf1);
    cudaGetSymbolAddress((void**)&whi,  g_whi);
    cudaGetSymbolAddress((void**)&wlo,  g_wlo);
    cudaGetSymbolAddress((void**)&tb,   g_t);
    cudaGetSymbolAddress((void**)&w16,  g_w16);
    cudaGetSymbolAddress((void**)&aw,   g_aw);
    cudaGetSymbolAddress((void**)&bnsc, g_bnsc);
    cudaGetSymbolAddress((void**)&bnsh, g_bnsh);

    cudaFuncSetAttribute(tconv_k<false>, cudaFuncAttributeMaxDynamicSharedMemorySize, TCONV_SMEM);
    cudaFuncSetAttribute(tconv_k<true >, cudaFuncAttributeMaxDynamicSharedMemorySize, TCONV_SMEM);

    // ---- prep ----
    wprep_k<<<144, 256>>>(w2,  whi + T_C2, wlo + T_C2, 64,  64);
    wprep_k<<<288, 256>>>(w3,  whi + T_C3, wlo + T_C3, 64,  128);
    wprep_k<<<576, 256>>>(w4,  whi + T_C4, wlo + T_C4, 128, 128);
    bn_prep_k<<<1, 128>>>(bn2g, bn2b, bn2m, bn2v, bnsc, bnsh, 128);

    // ---- encoder ----
    conv3x3_k<8,1><<<sgrid(416,416,4,64,8), 256>>>(x, w1, b1, buf0, 4, 3, 64, 416, 416);
    tconv_k<false><<<tgrid(416,416,4,64), 256, TCONV_SMEM>>>(buf0, whi+T_C2, wlo+T_C2, b2, buf1, 4, 64, 64, 416, 416, nullptr, nullptr);
    maxpool_k<<<4096, 256>>>(buf1, buf0, 4*64, 416, 416);
    tconv_k<false><<<tgrid(208,208,4,128), 256, TCONV_SMEM>>>(buf0, whi+T_C3, wlo+T_C3, b3, buf1, 4, 64, 128, 208, 208, nullptr, nullptr);
    tconv_k<false><<<tgrid(208,208,4,128), 256, TCONV_SMEM>>>(buf1, whi+T_C4, wlo+T_C4, b4, buf0, 4, 128, 128, 208, 208, nullptr, nullptr);
    maxpool_k<<<2048, 256>>>(buf0, buf1, 4*128, 208, 208);

    // remaining weight prep (needed by decoder only)
    wprep_k<<<576, 256>>>(dw1, whi + T_D1, wlo + T_D1, 128, 128);
    wprep_k<<<576, 256>>>(dw2, whi + T_D2, wlo + T_D2, 128, 128);
    wprep_k<<<288, 256>>>(dw3, whi + T_D3, wlo + T_D3, 128, 64);
    wprep_k<<<144, 256>>>(dw4, whi + T_D4, wlo + T_D4, 64,  64);
    bn_prep_k<<<1, 64 >>>(bn4g, bn4b, bn4m, bn4v, bnsc + 128, bnsh + 128, 64);

    // ---- block attention x2 (in-place on buf1) ----
    attn_t_k<<<1352, 256>>>(buf1, tb);
    attn_w1_k<<<ATTN_PB, 256>>>(buf1, tb, aw);
    attn_w2_k<<<1, 32>>>(aw, w16);
    attn_scale_k<<<2048, 256>>>(buf1, w16);
    attn_t_k<<<1352, 256>>>(buf1, tb);
    attn_w1_k<<<ATTN_PB, 256>>>(buf1, tb, aw);
    attn_w2_k<<<1, 32>>>(aw, w16);
    attn_scale_k<<<2048, 256>>>(buf1, w16);

    // ---- decoder ----
    tconv_k<false><<<tgrid(104,104,4,128), 256, TCONV_SMEM>>>(buf1, whi+T_D1, wlo+T_D1, db1, buf0, 4, 128, 128, 104, 104, nullptr, nullptr);
    tconv_k<true ><<<tgrid(104,104,4,128), 256, TCONV_SMEM>>>(buf0, whi+T_D2, wlo+T_D2, db2, buf1, 4, 128, 128, 104, 104, bnsc, bnsh);
    up2_k<<<2048, 256>>>(buf1, buf0, 4*128, 104, 104);
    tconv_k<false><<<tgrid(208,208,4,64), 256, TCONV_SMEM>>>(buf0, whi+T_D3, wlo+T_D3, db3, buf1, 4, 128, 64, 208, 208, nullptr, nullptr);
    tconv_k<true ><<<tgrid(208,208,4,64), 256, TCONV_SMEM>>>(buf1, whi+T_D4, wlo+T_D4, db4, buf0, 4, 64, 64, 208, 208, bnsc + 128, bnsh + 128);
    up2_k<<<4096, 256>>>(buf0, buf1, 4*64, 208, 208);
    conv3x3_k<2,2><<<sgrid(416,416,4,2,2), 256>>>(buf1, dw5, db5, out, 4, 64, 2, 416, 416);
}